// round 2
// baseline (speedup 1.0000x reference)
#include <cuda_runtime.h>
#include <math.h>

#define BTCH 2
#define NTOK 6400
#define NBINS 50
#define BINSZ 128
#define DDIM 32
#define FDIM 256
#define NKEY 100

// output packing (floats): [bins_split | x_features_binned | dm | msk_f_binned]
#define O1 12800ULL
#define O2 3289600ULL
#define O3 55718400ULL

__device__ int g_bin_idx[BTCH * NTOK];
__device__ int g_bins[BTCH * NTOK];

__device__ __forceinline__ float eluf(float x) { return x > 0.f ? x : expm1f(x); }

// ---------------------------------------------------------------------------
// Kernel A: LSH bin assignment. one thread per token.
// msk read as 32-bit words (bool was widened by the harness; works for both
// int32 0/1 and float32 0.0/1.0 representations).
// ---------------------------------------------------------------------------
__global__ void k_bins(const float* __restrict__ xd,
                       const int* __restrict__ msk,
                       const float* __restrict__ codebook)
{
    __shared__ float cb[25 * 32];  // cb[h*32+d] = codebook[d][h]
    int tid = threadIdx.x;
    for (int e = tid; e < 25 * 32; e += 128) {
        int h = e >> 5, d = e & 31;
        cb[e] = codebook[d * 100 + h];
    }
    __syncthreads();

    int gid = blockIdx.x * 128 + tid;  // 0 .. 12799
    const float* xr = xd + (size_t)gid * DDIM;
    float x[32];
#pragma unroll
    for (int c = 0; c < 8; c++) {
        float4 v = ((const float4*)xr)[c];
        x[c * 4 + 0] = v.x; x[c * 4 + 1] = v.y; x[c * 4 + 2] = v.z; x[c * 4 + 3] = v.w;
    }
    float mul[25];
#pragma unroll
    for (int h = 0; h < 25; h++) {
        float a0 = 0.f, a1 = 0.f, a2 = 0.f, a3 = 0.f;
#pragma unroll
        for (int d = 0; d < 32; d += 4) {
            a0 += x[d + 0] * cb[h * 32 + d + 0];
            a1 += x[d + 1] * cb[h * 32 + d + 1];
            a2 += x[d + 2] * cb[h * 32 + d + 2];
            a3 += x[d + 3] * cb[h * 32 + d + 3];
        }
        mul[h] = (a0 + a1) + (a2 + a3);
    }
    // argmax over [mul, -mul], first-occurrence tie rule (strict >)
    float best = -INFINITY; int arg = 0;
#pragma unroll
    for (int h = 0; h < 25; h++)
        if (mul[h] > best) { best = mul[h]; arg = h; }
#pragma unroll
    for (int h = 0; h < 25; h++) {
        float v = -mul[h];
        if (v > best) { best = v; arg = 25 + h; }
    }
    int key = arg + (msk[gid] != 0 ? 0 : (NBINS - 1));
    g_bin_idx[gid] = key;
}

// ---------------------------------------------------------------------------
// Kernel B: stable counting sort per batch -> bins_split (int + float out)
// 1 block per batch, 128 threads, 50 contiguous elements each.
// ---------------------------------------------------------------------------
__global__ void k_sort(float* __restrict__ out)
{
    __shared__ unsigned short hist[128][NKEY];
    __shared__ int key_start[NKEY];
    __shared__ int total[NKEY];

    int t = threadIdx.x;
    int b = blockIdx.x;
    const int* keys = g_bin_idx + b * NTOK;

    for (int k = 0; k < NKEY; k++) hist[t][k] = 0;
    __syncthreads();

    int base = t * 50;
    for (int i = 0; i < 50; i++) hist[t][keys[base + i]]++;
    __syncthreads();

    if (t < NKEY) {
        int run = 0;
        for (int t2 = 0; t2 < 128; t2++) {
            int c = hist[t2][t];
            hist[t2][t] = (unsigned short)run;  // prefix of earlier chunks
            run += c;
        }
        total[t] = run;
    }
    __syncthreads();
    if (t == 0) {
        int s = 0;
        for (int k = 0; k < NKEY; k++) { key_start[k] = s; s += total[k]; }
    }
    __syncthreads();

    int*   ob = g_bins + b * NTOK;
    float* of = out + (size_t)b * NTOK;  // bins_split section starts at 0
    for (int i = 0; i < 50; i++) {
        int n = base + i;
        int k = keys[n];
        int pos = key_start[k] + (int)hist[t][k];
        hist[t][k]++;
        ob[pos] = n;
        of[pos] = (float)n;
    }
}

// ---------------------------------------------------------------------------
// Kernel C: gather x_features_binned + msk_f_binned. 1 block per binned token.
// ---------------------------------------------------------------------------
__global__ void k_gather(const float* __restrict__ xf,
                         const int* __restrict__ msk,
                         float* __restrict__ out)
{
    int gid = blockIdx.x;           // 0 .. 12799
    int b = gid / NTOK;
    int src = g_bins[gid];
    const float4* s = (const float4*)(xf + ((size_t)(b * NTOK + src)) * FDIM);
    float4* d4 = (float4*)(out + O1 + (size_t)gid * FDIM);
    d4[threadIdx.x] = s[threadIdx.x];
    if (threadIdx.x == 0)
        out[O3 + gid] = (msk[b * NTOK + src] != 0) ? 1.f : 0.f;
}

// ---------------------------------------------------------------------------
// Kernel D: pairwise FFN -> dm.
// grid = 100 tiles x 4 j-quadrants. block = 512 threads (16 warps).
// Per warp: fixed i, 32 j's. Layer1 factored as U[i]+V[j].
// ---------------------------------------------------------------------------
__global__ void __launch_bounds__(512) k_dm(
    const float* __restrict__ xd, const int* __restrict__ msk,
    const float* __restrict__ W1, const float* __restrict__ b1,
    const float* __restrict__ W2, const float* __restrict__ b2,
    const float* __restrict__ W3, const float* __restrict__ b3,
    float* __restrict__ out)
{
    extern __shared__ float sm[];
    int*   idxS = (int*)sm;          // 128
    float* mS   = sm + 128;          // 128
    float* W1s  = sm + 256;          // 2048
    float* XdS  = sm + 2304;         // 128*36
    float* US   = sm + 6912;         // 128*36
    float* VS   = sm + 11520;        // 32*36
    float* H1   = sm + 12672;        // 16*32*36
    float* H2   = sm + 31104;        // 16*36

    int tid = threadIdx.x;
    int blk = blockIdx.x;
    int tile = blk >> 2;             // b*50 + bin
    int jb   = blk & 3;              // j quadrant (32 j's)
    int b    = tile / NBINS;
    int bin  = tile % NBINS;

    if (tid < 128) {
        int row = g_bins[b * NTOK + bin * BINSZ + tid];
        idxS[tid] = row;
        mS[tid] = (msk[b * NTOK + row] != 0) ? 1.f : 0.f;
    }
    for (int e = tid; e < 2048; e += 512) W1s[e] = W1[e];
    __syncthreads();

    // gather x_dist rows into smem (padded stride 36)
    {
        int i = tid >> 2, q = tid & 3;
        const float* src = xd + ((size_t)(b * NTOK + idxS[i])) * DDIM + q * 8;
        float4 v0 = ((const float4*)src)[0];
        float4 v1 = ((const float4*)src)[1];
        float* dst = XdS + i * 36 + q * 8;
        dst[0] = v0.x; dst[1] = v0.y; dst[2] = v0.z; dst[3] = v0.w;
        dst[4] = v1.x; dst[5] = v1.y; dst[6] = v1.z; dst[7] = v1.w;
    }
    __syncthreads();

    // U[i][o] = b1[o] + sum_d Xd[i][d] * W1[d][o]      (all 128 i)
    {
        int i = tid >> 2, og = (tid & 3) * 8;
        float acc[8];
#pragma unroll
        for (int c = 0; c < 8; c++) acc[c] = b1[og + c];
#pragma unroll
        for (int d = 0; d < 32; d++) {
            float xv = XdS[i * 36 + d];
            const float* wr = W1s + d * 32 + og;
#pragma unroll
            for (int c = 0; c < 8; c++) acc[c] += xv * wr[c];
        }
        float* u = US + i * 36 + og;
#pragma unroll
        for (int c = 0; c < 8; c++) u[c] = acc[c];
    }
    // V[jj][o] = sum_d Xd[jb*32+jj][d] * W1[32+d][o]   (32 j's of this quadrant)
    if (tid < 128) {
        int jj = tid >> 2, og = (tid & 3) * 8;
        int j = jb * 32 + jj;
        float acc[8];
#pragma unroll
        for (int c = 0; c < 8; c++) acc[c] = 0.f;
#pragma unroll
        for (int d = 0; d < 32; d++) {
            float xv = XdS[j * 36 + d];
            const float* wr = W1s + (32 + d) * 32 + og;
#pragma unroll
            for (int c = 0; c < 8; c++) acc[c] += xv * wr[c];
        }
        float* v = VS + jj * 36 + og;
#pragma unroll
        for (int c = 0; c < 8; c++) v[c] = acc[c];
    }

    // per-thread weights: lane owns output column `lane`
    int w = tid >> 5, lane = tid & 31;
    float w2r[32], w3r[32];
#pragma unroll
    for (int k = 0; k < 32; k++) {
        w2r[k] = W2[k * 32 + lane];
        w3r[k] = W3[k * 32 + lane];
    }
    float b2l = b2[lane], b3l = b3[lane];
    __syncthreads();

    float* h1w = H1 + w * (32 * 36);
    float* h2w = H2 + w * 36;

    for (int s = 0; s < 8; s++) {
        int i = s * 16 + w;
        float mi = mS[i];
        const float* Urow = US + i * 36;
        const float* Vrow = VS + lane * 36;

        // h1 for pair (i, j = jb*32 + lane)
#pragma unroll
        for (int k4 = 0; k4 < 8; k4++) {
            float4 u4 = *(const float4*)(Urow + k4 * 4);
            float4 v4 = *(const float4*)(Vrow + k4 * 4);
            float4 h;
            h.x = eluf(u4.x + v4.x);
            h.y = eluf(u4.y + v4.y);
            h.z = eluf(u4.z + v4.z);
            h.w = eluf(u4.w + v4.w);
            *(float4*)(h1w + lane * 36 + k4 * 4) = h;
        }
        __syncwarp();

        float* op = out + O2 + (((size_t)tile * BINSZ + i) * BINSZ + jb * 32) * 32 + lane;

        for (int rr = 0; rr < 32; rr++) {
            const float* hr = h1w + rr * 36;
            float a0 = 0.f, a1 = 0.f, a2 = 0.f, a3 = 0.f;
#pragma unroll
            for (int k4 = 0; k4 < 8; k4++) {
                float4 a = *(const float4*)(hr + k4 * 4);
                a0 += a.x * w2r[k4 * 4 + 0];
                a1 += a.y * w2r[k4 * 4 + 1];
                a2 += a.z * w2r[k4 * 4 + 2];
                a3 += a.w * w2r[k4 * 4 + 3];
            }
            float h2v = eluf((a0 + a1) + (a2 + a3) + b2l);
            h2w[lane] = h2v;
            __syncwarp();

            a0 = a1 = a2 = a3 = 0.f;
#pragma unroll
            for (int k4 = 0; k4 < 8; k4++) {
                float4 a = *(const float4*)(h2w + k4 * 4);
                a0 += a.x * w3r[k4 * 4 + 0];
                a1 += a.y * w3r[k4 * 4 + 1];
                a2 += a.z * w3r[k4 * 4 + 2];
                a3 += a.w * w3r[k4 * 4 + 3];
            }
            float dmv = eluf((a0 + a1) + (a2 + a3) + b3l) * (mi * mS[jb * 32 + rr]);
            op[(size_t)rr * 32] = dmv;
            __syncwarp();  // protect h2w (and h1w at s-loop wrap) reuse
        }
    }
}

// ---------------------------------------------------------------------------
extern "C" void kernel_launch(void* const* d_in, const int* in_sizes, int n_in,
                              void* d_out, int out_size)
{
    const float* xd  = (const float*)d_in[0];
    const float* xf  = (const float*)d_in[1];
    const int*   mk  = (const int*)d_in[2];
    const float* cb  = (const float*)d_in[3];
    const float* W1  = (const float*)d_in[4];
    const float* b1  = (const float*)d_in[5];
    const float* W2  = (const float*)d_in[6];
    const float* b2  = (const float*)d_in[7];
    const float* W3  = (const float*)d_in[8];
    const float* b3  = (const float*)d_in[9];
    float* out = (float*)d_out;

    k_bins<<<100, 128>>>(xd, mk, cb);
    k_sort<<<BTCH, 128>>>(out);
    k_gather<<<BTCH * NTOK, 64>>>(xf, mk, out);

    cudaFuncSetAttribute(k_dm, cudaFuncAttributeMaxDynamicSharedMemorySize, 126720);
    k_dm<<<400, 512, 126720>>>(xd, mk, W1, b1, W2, b2, W3, b3, out);
}

// round 3
// speedup vs baseline: 1.4083x; 1.4083x over previous
#include <cuda_runtime.h>
#include <math.h>

#define BTCH 2
#define NTOK 6400
#define NBINS 50
#define BINSZ 128
#define DDIM 32
#define FDIM 256
#define NKEY 100

// output packing (floats): [bins_split | x_features_binned | dm | msk_f_binned]
#define O1 12800ULL
#define O2 3289600ULL
#define O3 55718400ULL

__device__ int g_bin_idx[BTCH * NTOK];
__device__ int g_bins[BTCH * NTOK];

// fast elu: max(x,0) + (exp(min(x,0)) - 1);  exp(0)==1 exactly so branches fuse
__device__ __forceinline__ float eluf(float x) {
    return fmaxf(x, 0.f) + (__expf(fminf(x, 0.f)) - 1.f);
}

// packed f32x2 helpers (FFMA2 — PTX-only on sm_103a)
__device__ __forceinline__ unsigned long long pk2(float lo, float hi) {
    unsigned long long r;
    asm("mov.b64 %0, {%1, %2};" : "=l"(r) : "f"(lo), "f"(hi));
    return r;
}
__device__ __forceinline__ unsigned long long ffma2(unsigned long long a,
                                                    unsigned long long b,
                                                    unsigned long long c) {
    unsigned long long d;
    asm("fma.rn.f32x2 %0, %1, %2, %3;" : "=l"(d) : "l"(a), "l"(b), "l"(c));
    return d;
}
__device__ __forceinline__ float2 upk2(unsigned long long a) {
    float2 v;
    asm("mov.b64 {%0, %1}, %2;" : "=f"(v.x), "=f"(v.y) : "l"(a));
    return v;
}

// ---------------------------------------------------------------------------
// Kernel A: LSH bin assignment. one thread per token.
// ---------------------------------------------------------------------------
__global__ void k_bins(const float* __restrict__ xd,
                       const int* __restrict__ msk,
                       const float* __restrict__ codebook)
{
    __shared__ float cb[25 * 32];  // cb[h*32+d] = codebook[d][h]
    int tid = threadIdx.x;
    for (int e = tid; e < 25 * 32; e += 128) {
        int h = e >> 5, d = e & 31;
        cb[e] = codebook[d * 100 + h];
    }
    __syncthreads();

    int gid = blockIdx.x * 128 + tid;  // 0 .. 12799
    const float* xr = xd + (size_t)gid * DDIM;
    float x[32];
#pragma unroll
    for (int c = 0; c < 8; c++) {
        float4 v = ((const float4*)xr)[c];
        x[c * 4 + 0] = v.x; x[c * 4 + 1] = v.y; x[c * 4 + 2] = v.z; x[c * 4 + 3] = v.w;
    }
    float mul[25];
#pragma unroll
    for (int h = 0; h < 25; h++) {
        float a0 = 0.f, a1 = 0.f, a2 = 0.f, a3 = 0.f;
#pragma unroll
        for (int d = 0; d < 32; d += 4) {
            a0 += x[d + 0] * cb[h * 32 + d + 0];
            a1 += x[d + 1] * cb[h * 32 + d + 1];
            a2 += x[d + 2] * cb[h * 32 + d + 2];
            a3 += x[d + 3] * cb[h * 32 + d + 3];
        }
        mul[h] = (a0 + a1) + (a2 + a3);
    }
    float best = -INFINITY; int arg = 0;
#pragma unroll
    for (int h = 0; h < 25; h++)
        if (mul[h] > best) { best = mul[h]; arg = h; }
#pragma unroll
    for (int h = 0; h < 25; h++) {
        float v = -mul[h];
        if (v > best) { best = v; arg = 25 + h; }
    }
    int key = arg + (msk[gid] != 0 ? 0 : (NBINS - 1));
    g_bin_idx[gid] = key;
}

// ---------------------------------------------------------------------------
// Kernel B: stable counting sort per batch -> bins_split
// ---------------------------------------------------------------------------
__global__ void k_sort(float* __restrict__ out)
{
    __shared__ unsigned short hist[128][NKEY];
    __shared__ int key_start[NKEY];
    __shared__ int total[NKEY];

    int t = threadIdx.x;
    int b = blockIdx.x;
    const int* keys = g_bin_idx + b * NTOK;

    for (int k = 0; k < NKEY; k++) hist[t][k] = 0;
    __syncthreads();

    int base = t * 50;
    for (int i = 0; i < 50; i++) hist[t][keys[base + i]]++;
    __syncthreads();

    if (t < NKEY) {
        int run = 0;
        for (int t2 = 0; t2 < 128; t2++) {
            int c = hist[t2][t];
            hist[t2][t] = (unsigned short)run;
            run += c;
        }
        total[t] = run;
    }
    __syncthreads();
    if (t == 0) {
        int s = 0;
        for (int k = 0; k < NKEY; k++) { key_start[k] = s; s += total[k]; }
    }
    __syncthreads();

    int*   ob = g_bins + b * NTOK;
    float* of = out + (size_t)b * NTOK;
    for (int i = 0; i < 50; i++) {
        int n = base + i;
        int k = keys[n];
        int pos = key_start[k] + (int)hist[t][k];
        hist[t][k]++;
        ob[pos] = n;
        of[pos] = (float)n;
    }
}

// ---------------------------------------------------------------------------
// Kernel C: gather x_features_binned + msk_f_binned
// ---------------------------------------------------------------------------
__global__ void k_gather(const float* __restrict__ xf,
                         const int* __restrict__ msk,
                         float* __restrict__ out)
{
    int gid = blockIdx.x;           // 0 .. 12799
    int b = gid / NTOK;
    int src = g_bins[gid];
    const float4* s = (const float4*)(xf + ((size_t)(b * NTOK + src)) * FDIM);
    float4* d4 = (float4*)(out + O1 + (size_t)gid * FDIM);
    d4[threadIdx.x] = s[threadIdx.x];
    if (threadIdx.x == 0)
        out[O3 + gid] = (msk[b * NTOK + src] != 0) ? 1.f : 0.f;
}

// ---------------------------------------------------------------------------
// Kernel D: pairwise FFN -> dm.
// grid = 100 tiles x 4 j-quadrants. block = 256 threads (8 warps), 2 CTA/SM.
// Per warp: fixed i, 32 j's (16 i's per warp via s loop).
// Layer1 factored as U[i]+V[j]. Layers 2/3 via packed FFMA2 over k.
// smem floats:
//   idx[128] m[128] W1s[2048] Xd[128*36] U[128*36] V[32*36]
//   H1[8*32*36] H2[8*2*36]  => 22464 floats = 89856 B
// ---------------------------------------------------------------------------
__global__ void __launch_bounds__(256, 2) k_dm(
    const float* __restrict__ xd, const int* __restrict__ msk,
    const float* __restrict__ W1, const float* __restrict__ b1,
    const float* __restrict__ W2, const float* __restrict__ b2,
    const float* __restrict__ W3, const float* __restrict__ b3,
    float* __restrict__ out)
{
    extern __shared__ float sm[];
    int*   idxS = (int*)sm;          // 128
    float* mS   = sm + 128;          // 128
    float* W1s  = sm + 256;          // 2048
    float* XdS  = sm + 2304;         // 128*36
    float* US   = sm + 6912;         // 128*36
    float* VS   = sm + 11520;        // 32*36
    float* H1   = sm + 12672;        // 8*32*36
    float* H2   = sm + 21888;        // 8*2*36

    int tid = threadIdx.x;
    int blk = blockIdx.x;
    int tile = blk >> 2;             // b*50 + bin
    int jb   = blk & 3;              // j quadrant
    int b    = tile / NBINS;
    int bin  = tile % NBINS;

    if (tid < 128) {
        int row = g_bins[b * NTOK + bin * BINSZ + tid];
        idxS[tid] = row;
        mS[tid] = (msk[b * NTOK + row] != 0) ? 1.f : 0.f;
    }
    for (int e = tid; e < 2048; e += 256) W1s[e] = W1[e];
    __syncthreads();

    // gather x_dist rows into smem (padded stride 36); 2 threads per row
    {
        int i = tid >> 1, q = tid & 1;
        const float* src = xd + ((size_t)(b * NTOK + idxS[i])) * DDIM + q * 16;
        float* dst = XdS + i * 36 + q * 16;
#pragma unroll
        for (int c = 0; c < 4; c++) {
            float4 v = ((const float4*)src)[c];
            dst[c * 4 + 0] = v.x; dst[c * 4 + 1] = v.y;
            dst[c * 4 + 2] = v.z; dst[c * 4 + 3] = v.w;
        }
    }
    __syncthreads();

    // U[i][o] = b1[o] + sum_d Xd[i][d] * W1[d][o]  (512 tasks over 256 thr)
#pragma unroll
    for (int t2 = 0; t2 < 2; t2++) {
        int task = tid + t2 * 256;
        int i = task >> 2, og = (task & 3) * 8;
        float acc[8];
#pragma unroll
        for (int c = 0; c < 8; c++) acc[c] = b1[og + c];
#pragma unroll
        for (int d = 0; d < 32; d++) {
            float xv = XdS[i * 36 + d];
            const float* wr = W1s + d * 32 + og;
#pragma unroll
            for (int c = 0; c < 8; c++) acc[c] += xv * wr[c];
        }
        float* u = US + i * 36 + og;
#pragma unroll
        for (int c = 0; c < 8; c++) u[c] = acc[c];
    }
    // V[jj][o] = sum_d Xd[jb*32+jj][d] * W1[32+d][o]
    if (tid < 128) {
        int jj = tid >> 2, og = (tid & 3) * 8;
        int j = jb * 32 + jj;
        float acc[8];
#pragma unroll
        for (int c = 0; c < 8; c++) acc[c] = 0.f;
#pragma unroll
        for (int d = 0; d < 32; d++) {
            float xv = XdS[j * 36 + d];
            const float* wr = W1s + (32 + d) * 32 + og;
#pragma unroll
            for (int c = 0; c < 8; c++) acc[c] += xv * wr[c];
        }
        float* v = VS + jj * 36 + og;
#pragma unroll
        for (int c = 0; c < 8; c++) v[c] = acc[c];
    }

    // per-thread packed weights: lane owns output column `lane`, packed over k
    int w = tid >> 5, lane = tid & 31;
    unsigned long long w2p[16], w3p[16];
#pragma unroll
    for (int k2 = 0; k2 < 16; k2++) {
        w2p[k2] = pk2(W2[(2 * k2) * 32 + lane], W2[(2 * k2 + 1) * 32 + lane]);
        w3p[k2] = pk2(W3[(2 * k2) * 32 + lane], W3[(2 * k2 + 1) * 32 + lane]);
    }
    float b2l = b2[lane], b3l = b3[lane];
    __syncthreads();

    float* h1w = H1 + w * (32 * 36);
    float* h2w = H2 + w * 72;

    for (int s = 0; s < 16; s++) {
        int i = s * 8 + w;
        float mi = mS[i];
        const float* Urow = US + i * 36;
        const float* Vrow = VS + lane * 36;

        // h1 for pair (i, j = jb*32 + lane) -> smem row `lane`
#pragma unroll
        for (int k4 = 0; k4 < 8; k4++) {
            float4 u4 = *(const float4*)(Urow + k4 * 4);
            float4 v4 = *(const float4*)(Vrow + k4 * 4);
            float4 h;
            h.x = eluf(u4.x + v4.x);
            h.y = eluf(u4.y + v4.y);
            h.z = eluf(u4.z + v4.z);
            h.w = eluf(u4.w + v4.w);
            *(float4*)(h1w + lane * 36 + k4 * 4) = h;
        }
        __syncwarp();

        float* op = out + O2 + (((size_t)tile * BINSZ + i) * BINSZ + jb * 32) * 32 + lane;

        for (int rr = 0; rr < 32; rr++) {
            const float* hr = h1w + rr * 36;
            unsigned long long acc = pk2(b2l, 0.f);
#pragma unroll
            for (int k4 = 0; k4 < 8; k4++) {
                float4 a = *(const float4*)(hr + k4 * 4);
                acc = ffma2(pk2(a.x, a.y), w2p[k4 * 2 + 0], acc);
                acc = ffma2(pk2(a.z, a.w), w2p[k4 * 2 + 1], acc);
            }
            float2 sv = upk2(acc);
            float h2v = eluf(sv.x + sv.y);

            float* buf = h2w + (rr & 1) * 36;
            buf[lane] = h2v;
            __syncwarp();

            unsigned long long acc3 = pk2(b3l, 0.f);
#pragma unroll
            for (int k4 = 0; k4 < 8; k4++) {
                float4 a = *(const float4*)(buf + k4 * 4);
                acc3 = ffma2(pk2(a.x, a.y), w3p[k4 * 2 + 0], acc3);
                acc3 = ffma2(pk2(a.z, a.w), w3p[k4 * 2 + 1], acc3);
            }
            float2 s3 = upk2(acc3);
            float dmv = eluf(s3.x + s3.y) * (mi * mS[jb * 32 + rr]);
            op[(size_t)rr * 32] = dmv;
            // no trailing syncwarp: h2 is double-buffered, h1 rewrite is
            // ordered by the rr-loop's syncwarps + the one after h1 store
        }
    }
}

// ---------------------------------------------------------------------------
extern "C" void kernel_launch(void* const* d_in, const int* in_sizes, int n_in,
                              void* d_out, int out_size)
{
    const float* xd  = (const float*)d_in[0];
    const float* xf  = (const float*)d_in[1];
    const int*   mk  = (const int*)d_in[2];
    const float* cb  = (const float*)d_in[3];
    const float* W1  = (const float*)d_in[4];
    const float* b1  = (const float*)d_in[5];
    const float* W2  = (const float*)d_in[6];
    const float* b2  = (const float*)d_in[7];
    const float* W3  = (const float*)d_in[8];
    const float* b3  = (const float*)d_in[9];
    float* out = (float*)d_out;

    k_bins<<<100, 128>>>(xd, mk, cb);
    k_sort<<<BTCH, 128>>>(out);
    k_gather<<<BTCH * NTOK, 64>>>(xf, mk, out);

    cudaFuncSetAttribute(k_dm, cudaFuncAttributeMaxDynamicSharedMemorySize, 89856);
    k_dm<<<400, 256, 89856>>>(xd, mk, W1, b1, W2, b2, W3, b3, out);
}

// round 4
// speedup vs baseline: 1.5535x; 1.1031x over previous
#include <cuda_runtime.h>
#include <math.h>

#define BTCH 2
#define NTOK 6400
#define NBINS 50
#define BINSZ 128
#define DDIM 32
#define FDIM 256
#define NKEY 100

// output packing (floats): [bins_split | x_features_binned | dm | msk_f_binned]
#define O1 12800ULL
#define O2 3289600ULL
#define O3 55718400ULL

typedef unsigned long long ull;

__device__ int g_bin_idx[BTCH * NTOK];
__device__ int g_bins[BTCH * NTOK];

// fast elu: max(x,0) + (exp(min(x,0)) - 1);  exp(0)==1 exactly
__device__ __forceinline__ float eluf(float x) {
    return fmaxf(x, 0.f) + (__expf(fminf(x, 0.f)) - 1.f);
}

__device__ __forceinline__ ull pk2(float lo, float hi) {
    ull r;
    asm("mov.b64 %0, {%1, %2};" : "=l"(r) : "f"(lo), "f"(hi));
    return r;
}
__device__ __forceinline__ ull ffma2(ull a, ull b, ull c) {
    ull d;
    asm("fma.rn.f32x2 %0, %1, %2, %3;" : "=l"(d) : "l"(a), "l"(b), "l"(c));
    return d;
}
__device__ __forceinline__ float2 upk2(ull a) {
    float2 v;
    asm("mov.b64 {%0, %1}, %2;" : "=f"(v.x), "=f"(v.y) : "l"(a));
    return v;
}

// ---------------------------------------------------------------------------
// Kernel A: LSH bin assignment. one thread per token.
// ---------------------------------------------------------------------------
__global__ void k_bins(const float* __restrict__ xd,
                       const int* __restrict__ msk,
                       const float* __restrict__ codebook)
{
    __shared__ float cb[25 * 32];
    int tid = threadIdx.x;
    for (int e = tid; e < 25 * 32; e += 128) {
        int h = e >> 5, d = e & 31;
        cb[e] = codebook[d * 100 + h];
    }
    __syncthreads();

    int gid = blockIdx.x * 128 + tid;
    const float* xr = xd + (size_t)gid * DDIM;
    float x[32];
#pragma unroll
    for (int c = 0; c < 8; c++) {
        float4 v = ((const float4*)xr)[c];
        x[c * 4 + 0] = v.x; x[c * 4 + 1] = v.y; x[c * 4 + 2] = v.z; x[c * 4 + 3] = v.w;
    }
    float mul[25];
#pragma unroll
    for (int h = 0; h < 25; h++) {
        float a0 = 0.f, a1 = 0.f, a2 = 0.f, a3 = 0.f;
#pragma unroll
        for (int d = 0; d < 32; d += 4) {
            a0 += x[d + 0] * cb[h * 32 + d + 0];
            a1 += x[d + 1] * cb[h * 32 + d + 1];
            a2 += x[d + 2] * cb[h * 32 + d + 2];
            a3 += x[d + 3] * cb[h * 32 + d + 3];
        }
        mul[h] = (a0 + a1) + (a2 + a3);
    }
    float best = -INFINITY; int arg = 0;
#pragma unroll
    for (int h = 0; h < 25; h++)
        if (mul[h] > best) { best = mul[h]; arg = h; }
#pragma unroll
    for (int h = 0; h < 25; h++) {
        float v = -mul[h];
        if (v > best) { best = v; arg = 25 + h; }
    }
    g_bin_idx[gid] = arg + (msk[gid] != 0 ? 0 : (NBINS - 1));
}

// ---------------------------------------------------------------------------
// Kernel B: stable counting sort per batch -> bins_split
// ---------------------------------------------------------------------------
__global__ void k_sort(float* __restrict__ out)
{
    __shared__ unsigned short hist[128][NKEY];
    __shared__ int key_start[NKEY];
    __shared__ int total[NKEY];

    int t = threadIdx.x;
    int b = blockIdx.x;
    const int* keys = g_bin_idx + b * NTOK;

    for (int k = 0; k < NKEY; k++) hist[t][k] = 0;
    __syncthreads();

    int base = t * 50;
    for (int i = 0; i < 50; i++) hist[t][keys[base + i]]++;
    __syncthreads();

    if (t < NKEY) {
        int run = 0;
        for (int t2 = 0; t2 < 128; t2++) {
            int c = hist[t2][t];
            hist[t2][t] = (unsigned short)run;
            run += c;
        }
        total[t] = run;
    }
    __syncthreads();
    if (t == 0) {
        int s = 0;
        for (int k = 0; k < NKEY; k++) { key_start[k] = s; s += total[k]; }
    }
    __syncthreads();

    int*   ob = g_bins + b * NTOK;
    float* of = out + (size_t)b * NTOK;
    for (int i = 0; i < 50; i++) {
        int n = base + i;
        int k = keys[n];
        int pos = key_start[k] + (int)hist[t][k];
        hist[t][k]++;
        ob[pos] = n;
        of[pos] = (float)n;
    }
}

// ---------------------------------------------------------------------------
// Kernel C: gather x_features_binned + msk_f_binned. 4 rows per block.
// ---------------------------------------------------------------------------
__global__ void k_gather(const float* __restrict__ xf,
                         const int* __restrict__ msk,
                         float* __restrict__ out)
{
    int gid = blockIdx.x * 4 + (threadIdx.x >> 6);   // 0 .. 12799
    int lt = threadIdx.x & 63;
    int b = gid / NTOK;
    int src = g_bins[gid];
    const float4* s = (const float4*)(xf + ((size_t)(b * NTOK + src)) * FDIM);
    float4* d4 = (float4*)(out + O1 + (size_t)gid * FDIM);
    d4[lt] = s[lt];
    if (lt == 0)
        out[O3 + gid] = (msk[b * NTOK + src] != 0) ? 1.f : 0.f;
}

// ---------------------------------------------------------------------------
// Kernel D: pairwise FFN -> dm.
// grid = 100 tiles x 4 jb x 2 ih = 800 blocks. 256 threads (8 warps), 2 CTA/SM.
// Per warp: fixed i (8 per block-half), 32 j's. L1 factored U[i]+V[j].
// Layers 2/3: packed FFMA2, operands loaded straight from smem as f32x2.
// ---------------------------------------------------------------------------
__global__ void __launch_bounds__(256, 2) k_dm(
    const float* __restrict__ xd, const int* __restrict__ msk,
    const float* __restrict__ W1, const float* __restrict__ b1,
    const float* __restrict__ W2, const float* __restrict__ b2,
    const float* __restrict__ W3, const float* __restrict__ b3,
    float* __restrict__ out)
{
    extern __shared__ float sm[];
    int*   idxS = (int*)sm;          // 128
    float* mS   = sm + 128;          // 128
    float* W1s  = sm + 256;          // 2048
    float* XdS  = sm + 2304;         // 128*36
    float* US   = sm + 6912;         // 128*36 (only this block's 64 rows used)
    float* VS   = sm + 11520;        // 32*36
    float* H1   = sm + 12672;        // 8*32*36
    float* H2   = sm + 21888;        // 8*2*36

    int tid = threadIdx.x;
    int blk = blockIdx.x;
    int tile = blk >> 3;             // 0..99  (b*50 + bin)
    int jb   = (blk >> 1) & 3;       // j quadrant
    int ih   = blk & 1;              // i half
    int b    = tile / NBINS;
    int bin  = tile % NBINS;

    if (tid < 128) {
        int row = g_bins[b * NTOK + bin * BINSZ + tid];
        idxS[tid] = row;
        mS[tid] = (msk[b * NTOK + row] != 0) ? 1.f : 0.f;
    }
    for (int e = tid; e < 2048; e += 256) W1s[e] = W1[e];
    __syncthreads();

    // gather x_dist rows into smem (padded stride 36); 2 threads per row
    {
        int i = tid >> 1, q = tid & 1;
        const float* src = xd + ((size_t)(b * NTOK + idxS[i])) * DDIM + q * 16;
        float* dst = XdS + i * 36 + q * 16;
#pragma unroll
        for (int c = 0; c < 4; c++) {
            float4 v = ((const float4*)src)[c];
            dst[c * 4 + 0] = v.x; dst[c * 4 + 1] = v.y;
            dst[c * 4 + 2] = v.z; dst[c * 4 + 3] = v.w;
        }
    }
    __syncthreads();

    // U[i][o] for this block's 64 i-rows: 64*4 = 256 tasks, 1/thread
    {
        int i = ih * 64 + (tid >> 2);
        int og = (tid & 3) * 8;
        float acc[8];
#pragma unroll
        for (int c = 0; c < 8; c++) acc[c] = b1[og + c];
#pragma unroll
        for (int d = 0; d < 32; d++) {
            float xv = XdS[i * 36 + d];
            const float* wr = W1s + d * 32 + og;
#pragma unroll
            for (int c = 0; c < 8; c++) acc[c] += xv * wr[c];
        }
        float* u = US + i * 36 + og;
#pragma unroll
        for (int c = 0; c < 8; c++) u[c] = acc[c];
    }
    // V[jj][o] = sum_d Xd[jb*32+jj][d] * W1[32+d][o]
    if (tid < 128) {
        int jj = tid >> 2, og = (tid & 3) * 8;
        int j = jb * 32 + jj;
        float acc[8];
#pragma unroll
        for (int c = 0; c < 8; c++) acc[c] = 0.f;
#pragma unroll
        for (int d = 0; d < 32; d++) {
            float xv = XdS[j * 36 + d];
            const float* wr = W1s + (32 + d) * 32 + og;
#pragma unroll
            for (int c = 0; c < 8; c++) acc[c] += xv * wr[c];
        }
        float* v = VS + jj * 36 + og;
#pragma unroll
        for (int c = 0; c < 8; c++) v[c] = acc[c];
    }

    // per-thread packed weights: lane owns output column `lane`
    int w = tid >> 5, lane = tid & 31;
    ull w2p[16], w3p[16];
#pragma unroll
    for (int k2 = 0; k2 < 16; k2++) {
        w2p[k2] = pk2(W2[(2 * k2) * 32 + lane], W2[(2 * k2 + 1) * 32 + lane]);
        w3p[k2] = pk2(W3[(2 * k2) * 32 + lane], W3[(2 * k2 + 1) * 32 + lane]);
    }
    const ull b2p = pk2(b2[lane], 0.f);
    const ull b3p = pk2(b3[lane], 0.f);
    const ull zp  = pk2(0.f, 0.f);
    __syncthreads();

    float* h1w = H1 + w * (32 * 36);
    float* h2w = H2 + w * 72;

    for (int s = 0; s < 8; s++) {
        int i = ih * 64 + s * 8 + w;
        float mi = mS[i];
        const float* Urow = US + i * 36;
        const float* Vrow = VS + lane * 36;

        // h1 for pair (i, j = jb*32 + lane) -> smem row `lane`
#pragma unroll
        for (int k4 = 0; k4 < 8; k4++) {
            float4 u4 = *(const float4*)(Urow + k4 * 4);
            float4 v4 = *(const float4*)(Vrow + k4 * 4);
            float4 h;
            h.x = eluf(u4.x + v4.x);
            h.y = eluf(u4.y + v4.y);
            h.z = eluf(u4.z + v4.z);
            h.w = eluf(u4.w + v4.w);
            *(float4*)(h1w + lane * 36 + k4 * 4) = h;
        }
        __syncwarp();

        float* op = out + O2 + (((size_t)tile * BINSZ + i) * BINSZ + jb * 32) * 32 + lane;

        for (int rr = 0; rr < 32; rr++) {
            // layer 2: read h1 row rr as packed f32x2
            const ulonglong2* hr2 = (const ulonglong2*)(h1w + rr * 36);
            ull acc0 = b2p, acc1 = zp;
#pragma unroll
            for (int k8 = 0; k8 < 4; k8++) {
                ulonglong2 a = hr2[k8 * 2];
                ulonglong2 c = hr2[k8 * 2 + 1];
                acc0 = ffma2(a.x, w2p[k8 * 4 + 0], acc0);
                acc1 = ffma2(a.y, w2p[k8 * 4 + 1], acc1);
                acc0 = ffma2(c.x, w2p[k8 * 4 + 2], acc0);
                acc1 = ffma2(c.y, w2p[k8 * 4 + 3], acc1);
            }
            float2 s0 = upk2(acc0), s1 = upk2(acc1);
            float h2v = eluf((s0.x + s1.x) + (s0.y + s1.y));

            float* buf = h2w + (rr & 1) * 36;
            buf[lane] = h2v;
            __syncwarp();

            // layer 3
            const ulonglong2* br2 = (const ulonglong2*)buf;
            ull a0 = b3p, a1 = zp;
#pragma unroll
            for (int k8 = 0; k8 < 4; k8++) {
                ulonglong2 a = br2[k8 * 2];
                ulonglong2 c = br2[k8 * 2 + 1];
                a0 = ffma2(a.x, w3p[k8 * 4 + 0], a0);
                a1 = ffma2(a.y, w3p[k8 * 4 + 1], a1);
                a0 = ffma2(c.x, w3p[k8 * 4 + 2], a0);
                a1 = ffma2(c.y, w3p[k8 * 4 + 3], a1);
            }
            float2 t0 = upk2(a0), t1 = upk2(a1);
            float dmv = eluf((t0.x + t1.x) + (t0.y + t1.y)) * (mi * mS[jb * 32 + rr]);
            op[(size_t)rr * 32] = dmv;
        }
    }
}

// ---------------------------------------------------------------------------
extern "C" void kernel_launch(void* const* d_in, const int* in_sizes, int n_in,
                              void* d_out, int out_size)
{
    const float* xd  = (const float*)d_in[0];
    const float* xf  = (const float*)d_in[1];
    const int*   mk  = (const int*)d_in[2];
    const float* cb  = (const float*)d_in[3];
    const float* W1  = (const float*)d_in[4];
    const float* b1  = (const float*)d_in[5];
    const float* W2  = (const float*)d_in[6];
    const float* b2  = (const float*)d_in[7];
    const float* W3  = (const float*)d_in[8];
    const float* b3  = (const float*)d_in[9];
    float* out = (float*)d_out;

    k_bins<<<100, 128>>>(xd, mk, cb);
    k_sort<<<BTCH, 128>>>(out);
    k_gather<<<BTCH * NTOK / 4, 256>>>(xf, mk, out);

    cudaFuncSetAttribute(k_dm, cudaFuncAttributeMaxDynamicSharedMemorySize, 89856);
    k_dm<<<800, 256, 89856>>>(xd, mk, W1, b1, W2, b2, W3, b3, out);
}

// round 5
// speedup vs baseline: 2.2576x; 1.4532x over previous
#include <cuda_runtime.h>
#include <math.h>

#define BTCH 2
#define NTOK 6400
#define NBINS 50
#define BINSZ 128
#define DDIM 32
#define FDIM 256
#define NKEY 100

// output packing (floats): [bins_split | x_features_binned | dm | msk_f_binned]
#define O1 12800ULL
#define O2 3289600ULL
#define O3 55718400ULL

typedef unsigned long long ull;

__device__ int g_bin_idx[BTCH * NTOK];
__device__ int g_bins[BTCH * NTOK];

// fast elu: max(x,0) + (exp(min(x,0)) - 1);  exp(0)==1 exactly
__device__ __forceinline__ float eluf(float x) {
    return fmaxf(x, 0.f) + (__expf(fminf(x, 0.f)) - 1.f);
}

__device__ __forceinline__ ull pk2(float lo, float hi) {
    ull r;
    asm("mov.b64 %0, {%1, %2};" : "=l"(r) : "f"(lo), "f"(hi));
    return r;
}
__device__ __forceinline__ ull ffma2(ull a, ull b, ull c) {
    ull d;
    asm("fma.rn.f32x2 %0, %1, %2, %3;" : "=l"(d) : "l"(a), "l"(b), "l"(c));
    return d;
}
__device__ __forceinline__ float2 upk2(ull a) {
    float2 v;
    asm("mov.b64 {%0, %1}, %2;" : "=f"(v.x), "=f"(v.y) : "l"(a));
    return v;
}

// ---------------------------------------------------------------------------
// Kernel A: LSH bin assignment. one thread per token.
// ---------------------------------------------------------------------------
__global__ void k_bins(const float* __restrict__ xd,
                       const int* __restrict__ msk,
                       const float* __restrict__ codebook)
{
    __shared__ float cb[25 * 32];
    int tid = threadIdx.x;
    for (int e = tid; e < 25 * 32; e += 128) {
        int h = e >> 5, d = e & 31;
        cb[e] = codebook[d * 100 + h];
    }
    __syncthreads();

    int gid = blockIdx.x * 128 + tid;
    const float* xr = xd + (size_t)gid * DDIM;
    float x[32];
#pragma unroll
    for (int c = 0; c < 8; c++) {
        float4 v = ((const float4*)xr)[c];
        x[c * 4 + 0] = v.x; x[c * 4 + 1] = v.y; x[c * 4 + 2] = v.z; x[c * 4 + 3] = v.w;
    }
    float mul[25];
#pragma unroll
    for (int h = 0; h < 25; h++) {
        float a0 = 0.f, a1 = 0.f, a2 = 0.f, a3 = 0.f;
#pragma unroll
        for (int d = 0; d < 32; d += 4) {
            a0 += x[d + 0] * cb[h * 32 + d + 0];
            a1 += x[d + 1] * cb[h * 32 + d + 1];
            a2 += x[d + 2] * cb[h * 32 + d + 2];
            a3 += x[d + 3] * cb[h * 32 + d + 3];
        }
        mul[h] = (a0 + a1) + (a2 + a3);
    }
    float best = -INFINITY; int arg = 0;
#pragma unroll
    for (int h = 0; h < 25; h++)
        if (mul[h] > best) { best = mul[h]; arg = h; }
#pragma unroll
    for (int h = 0; h < 25; h++) {
        float v = -mul[h];
        if (v > best) { best = v; arg = 25 + h; }
    }
    g_bin_idx[gid] = arg + (msk[gid] != 0 ? 0 : (NBINS - 1));
}

// ---------------------------------------------------------------------------
// Kernel B: stable counting sort per batch -> bins_split
// ---------------------------------------------------------------------------
__global__ void k_sort(float* __restrict__ out)
{
    __shared__ unsigned short hist[128][NKEY];
    __shared__ int key_start[NKEY];
    __shared__ int total[NKEY];

    int t = threadIdx.x;
    int b = blockIdx.x;
    const int* keys = g_bin_idx + b * NTOK;

    for (int k = 0; k < NKEY; k++) hist[t][k] = 0;
    __syncthreads();

    int base = t * 50;
    for (int i = 0; i < 50; i++) hist[t][keys[base + i]]++;
    __syncthreads();

    if (t < NKEY) {
        int run = 0;
        for (int t2 = 0; t2 < 128; t2++) {
            int c = hist[t2][t];
            hist[t2][t] = (unsigned short)run;
            run += c;
        }
        total[t] = run;
    }
    __syncthreads();
    if (t == 0) {
        int s = 0;
        for (int k = 0; k < NKEY; k++) { key_start[k] = s; s += total[k]; }
    }
    __syncthreads();

    int*   ob = g_bins + b * NTOK;
    float* of = out + (size_t)b * NTOK;
    for (int i = 0; i < 50; i++) {
        int n = base + i;
        int k = keys[n];
        int pos = key_start[k] + (int)hist[t][k];
        hist[t][k]++;
        ob[pos] = n;
        of[pos] = (float)n;
    }
}

// ---------------------------------------------------------------------------
// Kernel C: gather x_features_binned + msk_f_binned. 4 rows per block.
// ---------------------------------------------------------------------------
__global__ void k_gather(const float* __restrict__ xf,
                         const int* __restrict__ msk,
                         float* __restrict__ out)
{
    int gid = blockIdx.x * 4 + (threadIdx.x >> 6);   // 0 .. 12799
    int lt = threadIdx.x & 63;
    int b = gid / NTOK;
    int src = g_bins[gid];
    const float4* s = (const float4*)(xf + ((size_t)(b * NTOK + src)) * FDIM);
    float4* d4 = (float4*)(out + O1 + (size_t)gid * FDIM);
    d4[lt] = s[lt];
    if (lt == 0)
        out[O3 + gid] = (msk[b * NTOK + src] != 0) ? 1.f : 0.f;
}

// ---------------------------------------------------------------------------
// Kernel D: pairwise FFN -> dm, with mask sparsity exploitation.
// dm[i][j][:] == 0 whenever mi==0 or mj==0 (elu output finite, x*0 == +-0),
// so only active(i) x active(j) pairs are computed; the rest are zero-filled.
// grid = 100 tiles x 4 jb x 2 ih = 800 blocks, 256 threads, 2 CTA/SM.
// ---------------------------------------------------------------------------
__global__ void __launch_bounds__(256, 2) k_dm(
    const float* __restrict__ xd, const int* __restrict__ msk,
    const float* __restrict__ W1, const float* __restrict__ b1,
    const float* __restrict__ W2, const float* __restrict__ b2,
    const float* __restrict__ W3, const float* __restrict__ b3,
    float* __restrict__ out)
{
    extern __shared__ float sm[];
    int*   idxS = (int*)sm;          // 128
    float* mS   = sm + 128;          // 128
    float* W1s  = sm + 256;          // 2048
    float* XdS  = sm + 2304;         // 128*36
    float* US   = sm + 6912;         // 128*36 (only this block's 64 rows used)
    float* VS   = sm + 11520;        // 32*36
    float* H1   = sm + 12672;        // 8*32*36
    float* H2   = sm + 21888;        // 8*2*36
    int*   actJ = (int*)(sm + 22464);   // 32
    int*   inactJ = (int*)(sm + 22496); // 32
    int*   nJp  = (int*)(sm + 22528);   // 1

    int tid = threadIdx.x;
    int blk = blockIdx.x;
    int tile = blk >> 3;             // 0..99  (b*50 + bin)
    int jb   = (blk >> 1) & 3;       // j quadrant
    int ih   = blk & 1;              // i half
    int b    = tile / NBINS;
    int bin  = tile % NBINS;

    if (tid < 128) {
        int row = g_bins[b * NTOK + bin * BINSZ + tid];
        idxS[tid] = row;
        mS[tid] = (msk[b * NTOK + row] != 0) ? 1.f : 0.f;
    }
    for (int e = tid; e < 2048; e += 256) W1s[e] = W1[e];
    __syncthreads();

    // active/inactive j lists for this quadrant (warp 0)
    if (tid < 32) {
        int mj = (mS[jb * 32 + tid] != 0.f);
        unsigned bal = __ballot_sync(0xffffffffu, mj);
        int pos = __popc(bal & ((1u << tid) - 1u));
        if (mj) actJ[pos] = tid;
        else    inactJ[tid - pos] = tid;
        if (tid == 0) nJp[0] = __popc(bal);
    }

    // gather x_dist rows into smem (padded stride 36); 2 threads per row
    {
        int i = tid >> 1, q = tid & 1;
        const float* src = xd + ((size_t)(b * NTOK + idxS[i])) * DDIM + q * 16;
        float* dst = XdS + i * 36 + q * 16;
#pragma unroll
        for (int c = 0; c < 4; c++) {
            float4 v = ((const float4*)src)[c];
            dst[c * 4 + 0] = v.x; dst[c * 4 + 1] = v.y;
            dst[c * 4 + 2] = v.z; dst[c * 4 + 3] = v.w;
        }
    }
    __syncthreads();

    int nJ = nJp[0];
    int nInact = 32 - nJ;

    if (nJ > 0) {
        // U[i][o] for this block's 64 i-rows
        int i = ih * 64 + (tid >> 2);
        int og = (tid & 3) * 8;
        float acc[8];
#pragma unroll
        for (int c = 0; c < 8; c++) acc[c] = b1[og + c];
#pragma unroll
        for (int d = 0; d < 32; d++) {
            float xv = XdS[i * 36 + d];
            const float* wr = W1s + d * 32 + og;
#pragma unroll
            for (int c = 0; c < 8; c++) acc[c] += xv * wr[c];
        }
        float* u = US + i * 36 + og;
#pragma unroll
        for (int c = 0; c < 8; c++) u[c] = acc[c];

        // V[jj][o]
        if (tid < 128) {
            int jj = tid >> 2;
            int j = jb * 32 + jj;
            float accv[8];
#pragma unroll
            for (int c = 0; c < 8; c++) accv[c] = 0.f;
#pragma unroll
            for (int d = 0; d < 32; d++) {
                float xv = XdS[j * 36 + d];
                const float* wr = W1s + (32 + d) * 32 + og;
#pragma unroll
                for (int c = 0; c < 8; c++) accv[c] += xv * wr[c];
            }
            float* v = VS + jj * 36 + og;
#pragma unroll
            for (int c = 0; c < 8; c++) v[c] = accv[c];
        }
    }

    // per-thread packed weights: lane owns output column `lane`
    int w = tid >> 5, lane = tid & 31;
    ull w2p[16], w3p[16];
#pragma unroll
    for (int k2 = 0; k2 < 16; k2++) {
        w2p[k2] = pk2(W2[(2 * k2) * 32 + lane], W2[(2 * k2 + 1) * 32 + lane]);
        w3p[k2] = pk2(W3[(2 * k2) * 32 + lane], W3[(2 * k2 + 1) * 32 + lane]);
    }
    const ull b2p = pk2(b2[lane], 0.f);
    const ull b3p = pk2(b3[lane], 0.f);
    const ull zp  = pk2(0.f, 0.f);
    const float4 z4 = make_float4(0.f, 0.f, 0.f, 0.f);
    __syncthreads();

    float* h1w = H1 + w * (32 * 36);
    float* h2w = H2 + w * 72;

    for (int s = 0; s < 8; s++) {
        int i = ih * 64 + s * 8 + w;
        // row base for (tile, i, j=jb*32) in dm
        float* rowbase = out + O2 + (((size_t)tile * BINSZ + i) * BINSZ + jb * 32) * 32;

        if (mS[i] == 0.f) {
            // whole i-row masked: 32 zero rows, one per lane
            float4* rp = (float4*)(rowbase + lane * 32);
#pragma unroll
            for (int c = 0; c < 8; c++) rp[c] = z4;
            continue;
        }

        // zero-fill inactive j rows
        for (int t = lane; t < nInact; t += 32) {
            float4* rp = (float4*)(rowbase + inactJ[t] * 32);
#pragma unroll
            for (int c = 0; c < 8; c++) rp[c] = z4;
        }
        if (nJ == 0) continue;

        const float* Urow = US + i * 36;
        const float* Vrow = VS + lane * 36;

        // h1 for pair (i, j = jb*32 + lane) -> smem row `lane`
#pragma unroll
        for (int k4 = 0; k4 < 8; k4++) {
            float4 u4 = *(const float4*)(Urow + k4 * 4);
            float4 v4 = *(const float4*)(Vrow + k4 * 4);
            float4 h;
            h.x = eluf(u4.x + v4.x);
            h.y = eluf(u4.y + v4.y);
            h.z = eluf(u4.z + v4.z);
            h.w = eluf(u4.w + v4.w);
            *(float4*)(h1w + lane * 36 + k4 * 4) = h;
        }
        __syncwarp();

        float* op = rowbase + lane;

        for (int t = 0; t < nJ; t++) {
            int rr = actJ[t];
            // layer 2: read h1 row rr as packed f32x2
            const ulonglong2* hr2 = (const ulonglong2*)(h1w + rr * 36);
            ull acc0 = b2p, acc1 = zp;
#pragma unroll
            for (int k8 = 0; k8 < 4; k8++) {
                ulonglong2 a = hr2[k8 * 2];
                ulonglong2 c = hr2[k8 * 2 + 1];
                acc0 = ffma2(a.x, w2p[k8 * 4 + 0], acc0);
                acc1 = ffma2(a.y, w2p[k8 * 4 + 1], acc1);
                acc0 = ffma2(c.x, w2p[k8 * 4 + 2], acc0);
                acc1 = ffma2(c.y, w2p[k8 * 4 + 3], acc1);
            }
            float2 s0 = upk2(acc0), s1 = upk2(acc1);
            float h2v = eluf((s0.x + s1.x) + (s0.y + s1.y));

            float* buf = h2w + (t & 1) * 36;
            buf[lane] = h2v;
            __syncwarp();

            // layer 3 (mi=mj=1 on this path, masks drop out)
            const ulonglong2* br2 = (const ulonglong2*)buf;
            ull a0 = b3p, a1 = zp;
#pragma unroll
            for (int k8 = 0; k8 < 4; k8++) {
                ulonglong2 a = br2[k8 * 2];
                ulonglong2 c = br2[k8 * 2 + 1];
                a0 = ffma2(a.x, w3p[k8 * 4 + 0], a0);
                a1 = ffma2(a.y, w3p[k8 * 4 + 1], a1);
                a0 = ffma2(c.x, w3p[k8 * 4 + 2], a0);
                a1 = ffma2(c.y, w3p[k8 * 4 + 3], a1);
            }
            float2 t0 = upk2(a0), t1 = upk2(a1);
            op[(size_t)rr * 32] = eluf((t0.x + t1.x) + (t0.y + t1.y));
        }
    }
}

// ---------------------------------------------------------------------------
extern "C" void kernel_launch(void* const* d_in, const int* in_sizes, int n_in,
                              void* d_out, int out_size)
{
    const float* xd  = (const float*)d_in[0];
    const float* xf  = (const float*)d_in[1];
    const int*   mk  = (const int*)d_in[2];
    const float* cb  = (const float*)d_in[3];
    const float* W1  = (const float*)d_in[4];
    const float* b1  = (const float*)d_in[5];
    const float* W2  = (const float*)d_in[6];
    const float* b2  = (const float*)d_in[7];
    const float* W3  = (const float*)d_in[8];
    const float* b3  = (const float*)d_in[9];
    float* out = (float*)d_out;

    k_bins<<<100, 128>>>(xd, mk, cb);
    k_sort<<<BTCH, 128>>>(out);
    k_gather<<<BTCH * NTOK / 4, 256>>>(xf, mk, out);

    cudaFuncSetAttribute(k_dm, cudaFuncAttributeMaxDynamicSharedMemorySize, 90116);
    k_dm<<<800, 256, 90116>>>(xd, mk, W1, b1, W2, b2, W3, b3, out);
}

// round 6
// speedup vs baseline: 2.5575x; 1.1329x over previous
#include <cuda_runtime.h>
#include <math.h>

#define BTCH 2
#define NTOK 6400
#define NBINS 50
#define BINSZ 128
#define DDIM 32
#define FDIM 256
#define NKEY 100

// output packing (floats): [bins_split | x_features_binned | dm | msk_f_binned]
#define O1 12800ULL
#define O2 3289600ULL
#define O3 55718400ULL

typedef unsigned long long ull;

__device__ int g_bin_idx[BTCH * NTOK];
__device__ int g_bins[BTCH * NTOK];

// fast elu: max(x,0) + (exp(min(x,0)) - 1);  exp(0)==1 exactly
__device__ __forceinline__ float eluf(float x) {
    return fmaxf(x, 0.f) + (__expf(fminf(x, 0.f)) - 1.f);
}

__device__ __forceinline__ ull pk2(float lo, float hi) {
    ull r;
    asm("mov.b64 %0, {%1, %2};" : "=l"(r) : "f"(lo), "f"(hi));
    return r;
}
__device__ __forceinline__ ull ffma2(ull a, ull b, ull c) {
    ull d;
    asm("fma.rn.f32x2 %0, %1, %2, %3;" : "=l"(d) : "l"(a), "l"(b), "l"(c));
    return d;
}
__device__ __forceinline__ float2 upk2(ull a) {
    float2 v;
    asm("mov.b64 {%0, %1}, %2;" : "=f"(v.x), "=f"(v.y) : "l"(a));
    return v;
}

// ---------------------------------------------------------------------------
// Kernel A: LSH bin assignment. one thread per token.
// ---------------------------------------------------------------------------
__global__ void k_bins(const float* __restrict__ xd,
                       const int* __restrict__ msk,
                       const float* __restrict__ codebook)
{
    __shared__ float cb[25 * 32];
    int tid = threadIdx.x;
    for (int e = tid; e < 25 * 32; e += 128) {
        int h = e >> 5, d = e & 31;
        cb[e] = codebook[d * 100 + h];
    }
    __syncthreads();

    int gid = blockIdx.x * 128 + tid;
    const float* xr = xd + (size_t)gid * DDIM;
    float x[32];
#pragma unroll
    for (int c = 0; c < 8; c++) {
        float4 v = ((const float4*)xr)[c];
        x[c * 4 + 0] = v.x; x[c * 4 + 1] = v.y; x[c * 4 + 2] = v.z; x[c * 4 + 3] = v.w;
    }
    float mul[25];
#pragma unroll
    for (int h = 0; h < 25; h++) {
        float a0 = 0.f, a1 = 0.f, a2 = 0.f, a3 = 0.f;
#pragma unroll
        for (int d = 0; d < 32; d += 4) {
            a0 += x[d + 0] * cb[h * 32 + d + 0];
            a1 += x[d + 1] * cb[h * 32 + d + 1];
            a2 += x[d + 2] * cb[h * 32 + d + 2];
            a3 += x[d + 3] * cb[h * 32 + d + 3];
        }
        mul[h] = (a0 + a1) + (a2 + a3);
    }
    float best = -INFINITY; int arg = 0;
#pragma unroll
    for (int h = 0; h < 25; h++)
        if (mul[h] > best) { best = mul[h]; arg = h; }
#pragma unroll
    for (int h = 0; h < 25; h++) {
        float v = -mul[h];
        if (v > best) { best = v; arg = 25 + h; }
    }
    g_bin_idx[gid] = arg + (msk[gid] != 0 ? 0 : (NBINS - 1));
}

// ---------------------------------------------------------------------------
// Kernel B: stable counting sort per batch -> bins_split
// ---------------------------------------------------------------------------
__global__ void k_sort(float* __restrict__ out)
{
    __shared__ unsigned short hist[128][NKEY];
    __shared__ int key_start[NKEY];
    __shared__ int total[NKEY];

    int t = threadIdx.x;
    int b = blockIdx.x;
    const int* keys = g_bin_idx + b * NTOK;

    for (int k = 0; k < NKEY; k++) hist[t][k] = 0;
    __syncthreads();

    int base = t * 50;
    for (int i = 0; i < 50; i++) hist[t][keys[base + i]]++;
    __syncthreads();

    if (t < NKEY) {
        int run = 0;
        for (int t2 = 0; t2 < 128; t2++) {
            int c = hist[t2][t];
            hist[t2][t] = (unsigned short)run;
            run += c;
        }
        total[t] = run;
    }
    __syncthreads();
    if (t == 0) {
        int s = 0;
        for (int k = 0; k < NKEY; k++) { key_start[k] = s; s += total[k]; }
    }
    __syncthreads();

    int*   ob = g_bins + b * NTOK;
    float* of = out + (size_t)b * NTOK;
    for (int i = 0; i < 50; i++) {
        int n = base + i;
        int k = keys[n];
        int pos = key_start[k] + (int)hist[t][k];
        hist[t][k]++;
        ob[pos] = n;
        of[pos] = (float)n;
    }
}

// ---------------------------------------------------------------------------
// Kernel C: gather x_features_binned + msk_f_binned. 4 rows per block.
// ---------------------------------------------------------------------------
__global__ void k_gather(const float* __restrict__ xf,
                         const int* __restrict__ msk,
                         float* __restrict__ out)
{
    int gid = blockIdx.x * 4 + (threadIdx.x >> 6);   // 0 .. 12799
    int lt = threadIdx.x & 63;
    int b = gid / NTOK;
    int src = g_bins[gid];
    const float4* s = (const float4*)(xf + ((size_t)(b * NTOK + src)) * FDIM);
    float4* d4 = (float4*)(out + O1 + (size_t)gid * FDIM);
    d4[lt] = s[lt];
    if (lt == 0)
        out[O3 + gid] = (msk[b * NTOK + src] != 0) ? 1.f : 0.f;
}

// ---------------------------------------------------------------------------
// Kernel D: pairwise FFN -> dm. Lane-owns-j formulation: zero smem round trips
// for h1/h2, no intra-warp barriers. Weights broadcast-streamed from smem.
// grid = 100 tiles x 4 jb x 2 ih = 800 blocks, 256 threads, 2 CTA/SM.
// ---------------------------------------------------------------------------
__global__ void __launch_bounds__(256, 2) k_dm(
    const float* __restrict__ xd, const int* __restrict__ msk,
    const float* __restrict__ W1, const float* __restrict__ b1,
    const float* __restrict__ W2, const float* __restrict__ b2,
    const float* __restrict__ W3, const float* __restrict__ b3,
    float* __restrict__ out)
{
    extern __shared__ float sm[];
    int*   idxS = (int*)sm;          // 128
    float* mS   = sm + 128;          // 128
    float* W1s  = sm + 256;          // 2048
    float* W2s  = sm + 2304;         // 1024  (row k = 32 floats = 16 ull pairs)
    float* W3s  = sm + 3328;         // 1024
    float* b2s  = sm + 4352;         // 32
    float* b3s  = sm + 4384;         // 32
    float* XdS  = sm + 4416;         // 128*36 = 4608
    float* US   = sm + 9024;         // 128*36 = 4608
    float* VTS  = sm + 13632;        // 32k x 32j transposed = 1024
    // total 14656 floats = 58624 B

    int tid = threadIdx.x;
    int blk = blockIdx.x;
    int tile = blk >> 3;             // 0..99  (b*50 + bin)
    int jb   = (blk >> 1) & 3;       // j quadrant
    int ih   = blk & 1;              // i half
    int b    = tile / NBINS;
    int bin  = tile % NBINS;

    int w = tid >> 5, lane = tid & 31;

    if (tid < 128) {
        int row = g_bins[b * NTOK + bin * BINSZ + tid];
        idxS[tid] = row;
        mS[tid] = (msk[b * NTOK + row] != 0) ? 1.f : 0.f;
    }
    __syncthreads();

    // per-thread mask of this quadrant's j = lane; warp-wide activity mask
    float mjl = mS[jb * 32 + lane];
    unsigned act = __ballot_sync(0xffffffffu, mjl != 0.f);

    if (act == 0) {
        // fully masked quadrant: zero-fill 64 i-rows x 32 j x 32 cols
        float4 z4 = make_float4(0.f, 0.f, 0.f, 0.f);
        for (int i = 0; i < 64; i++) {
            float4* rp = (float4*)(out + O2 +
                (((size_t)tile * BINSZ + ih * 64 + i) * BINSZ + jb * 32) * 32);
            rp[tid] = z4;
        }
        return;
    }

    // stage weights
    for (int e = tid; e < 2048; e += 256) W1s[e] = W1[e];
    for (int e = tid; e < 1024; e += 256) { W2s[e] = W2[e]; W3s[e] = W3[e]; }
    if (tid < 32) { b2s[tid] = b2[tid]; b3s[tid] = b3[tid]; }

    // gather x_dist rows into smem (padded stride 36); 2 threads per row
    {
        int i = tid >> 1, q = tid & 1;
        const float* src = xd + ((size_t)(b * NTOK + idxS[i])) * DDIM + q * 16;
        float* dst = XdS + i * 36 + q * 16;
#pragma unroll
        for (int c = 0; c < 4; c++) {
            float4 v = ((const float4*)src)[c];
            dst[c * 4 + 0] = v.x; dst[c * 4 + 1] = v.y;
            dst[c * 4 + 2] = v.z; dst[c * 4 + 3] = v.w;
        }
    }
    __syncthreads();

    // U[i][o] for this block's 64 i-rows (256 tasks: i x og)
    {
        int i = ih * 64 + (tid >> 2);
        int og = (tid & 3) * 8;
        float acc[8];
#pragma unroll
        for (int c = 0; c < 8; c++) acc[c] = b1[og + c];
#pragma unroll
        for (int d = 0; d < 32; d++) {
            float xv = XdS[i * 36 + d];
            const float* wr = W1s + d * 32 + og;
#pragma unroll
            for (int c = 0; c < 8; c++) acc[c] += xv * wr[c];
        }
        float* u = US + i * 36 + og;
#pragma unroll
        for (int c = 0; c < 8; c++) u[c] = acc[c];
    }
    // V^T[o][j]: thread (jj, og) computes V[j][og..og+8), stores transposed
    if (tid < 128) {
        int jj = tid >> 2, og = (tid & 3) * 8;
        int j = jb * 32 + jj;
        float accv[8];
#pragma unroll
        for (int c = 0; c < 8; c++) accv[c] = 0.f;
#pragma unroll
        for (int d = 0; d < 32; d++) {
            float xv = XdS[j * 36 + d];
            const float* wr = W1s + (32 + d) * 32 + og;
#pragma unroll
            for (int c = 0; c < 8; c++) accv[c] += xv * wr[c];
        }
#pragma unroll
        for (int c = 0; c < 8; c++) VTS[(og + c) * 32 + jj] = accv[c];
    }
    __syncthreads();

    const ulonglong2* b2v = (const ulonglong2*)b2s;
    const ulonglong2* b3v = (const ulonglong2*)b3s;
    const float4 z4 = make_float4(0.f, 0.f, 0.f, 0.f);

    for (int s = 0; s < 8; s++) {
        int i = ih * 64 + s * 8 + w;
        float* rowp = out + O2 +
            ((((size_t)tile * BINSZ + i) * BINSZ + jb * 32 + lane) * 32);

        if (mS[i] == 0.f) {
            float4* rp = (float4*)rowp;
#pragma unroll
            for (int c = 0; c < 8; c++) rp[c] = z4;
            continue;
        }

        // h1[k] = elu(U[i][k] + V[lane][k])   (U broadcast, VT conflict-free)
        float h1v[32];
        {
            const float4* U4 = (const float4*)(US + i * 36);
#pragma unroll
            for (int c4 = 0; c4 < 8; c4++) {
                float4 u = U4[c4];
                h1v[c4 * 4 + 0] = eluf(u.x + VTS[(c4 * 4 + 0) * 32 + lane]);
                h1v[c4 * 4 + 1] = eluf(u.y + VTS[(c4 * 4 + 1) * 32 + lane]);
                h1v[c4 * 4 + 2] = eluf(u.z + VTS[(c4 * 4 + 2) * 32 + lane]);
                h1v[c4 * 4 + 3] = eluf(u.w + VTS[(c4 * 4 + 3) * 32 + lane]);
            }
        }

        // layer 2: acc[o2] = (h2[2o2], h2[2o2+1]) accumulated over k
        ull acc[16];
#pragma unroll
        for (int q = 0; q < 8; q++) {
            ulonglong2 bv = b2v[q];
            acc[2 * q] = bv.x; acc[2 * q + 1] = bv.y;
        }
#pragma unroll
        for (int k = 0; k < 32; k++) {
            ull hd = pk2(h1v[k], h1v[k]);
            const ulonglong2* wrow = (const ulonglong2*)(W2s + k * 32);
#pragma unroll
            for (int q = 0; q < 8; q++) {
                ulonglong2 wv = wrow[q];
                acc[2 * q]     = ffma2(hd, wv.x, acc[2 * q]);
                acc[2 * q + 1] = ffma2(hd, wv.y, acc[2 * q + 1]);
            }
        }
        float h2v[32];
#pragma unroll
        for (int o2 = 0; o2 < 16; o2++) {
            float2 f = upk2(acc[o2]);
            h2v[2 * o2]     = eluf(f.x);
            h2v[2 * o2 + 1] = eluf(f.y);
        }

        // layer 3
#pragma unroll
        for (int q = 0; q < 8; q++) {
            ulonglong2 bv = b3v[q];
            acc[2 * q] = bv.x; acc[2 * q + 1] = bv.y;
        }
#pragma unroll
        for (int k = 0; k < 32; k++) {
            ull hd = pk2(h2v[k], h2v[k]);
            const ulonglong2* wrow = (const ulonglong2*)(W3s + k * 32);
#pragma unroll
            for (int q = 0; q < 8; q++) {
                ulonglong2 wv = wrow[q];
                acc[2 * q]     = ffma2(hd, wv.x, acc[2 * q]);
                acc[2 * q + 1] = ffma2(hd, wv.y, acc[2 * q + 1]);
            }
        }

        // final elu, mask by mj (exact 0/1), store 32 contiguous floats
        float4* rp = (float4*)rowp;
#pragma unroll
        for (int q = 0; q < 8; q++) {
            float2 fa = upk2(acc[2 * q]);
            float2 fb = upk2(acc[2 * q + 1]);
            float4 r;
            r.x = eluf(fa.x) * mjl;
            r.y = eluf(fa.y) * mjl;
            r.z = eluf(fb.x) * mjl;
            r.w = eluf(fb.y) * mjl;
            rp[q] = r;
        }
    }
}

// ---------------------------------------------------------------------------
extern "C" void kernel_launch(void* const* d_in, const int* in_sizes, int n_in,
                              void* d_out, int out_size)
{
    const float* xd  = (const float*)d_in[0];
    const float* xf  = (const float*)d_in[1];
    const int*   mk  = (const int*)d_in[2];
    const float* cb  = (const float*)d_in[3];
    const float* W1  = (const float*)d_in[4];
    const float* b1  = (const float*)d_in[5];
    const float* W2  = (const float*)d_in[6];
    const float* b2  = (const float*)d_in[7];
    const float* W3  = (const float*)d_in[8];
    const float* b3  = (const float*)d_in[9];
    float* out = (float*)d_out;

    k_bins<<<100, 128>>>(xd, mk, cb);
    k_sort<<<BTCH, 128>>>(out);
    k_gather<<<BTCH * NTOK / 4, 256>>>(xf, mk, out);

    cudaFuncSetAttribute(k_dm, cudaFuncAttributeMaxDynamicSharedMemorySize, 58624);
    k_dm<<<800, 256, 58624>>>(xd, mk, W1, b1, W2, b2, W3, b3, out);
}

// round 7
// speedup vs baseline: 2.8078x; 1.0979x over previous
#include <cuda_runtime.h>
#include <math.h>

#define BTCH 2
#define NTOK 6400
#define NBINS 50
#define BINSZ 128
#define DDIM 32
#define FDIM 256
#define NKEY 100

// output packing (floats): [bins_split | x_features_binned | dm | msk_f_binned]
#define O1 12800ULL
#define O2 3289600ULL
#define O3 55718400ULL

#define DM_BLOCKS 1600
#define GATHER_BLOCKS 200

typedef unsigned long long ull;

__device__ int g_bin_idx[BTCH * NTOK];
__device__ int g_bins[BTCH * NTOK];

// fast elu: max(x,0) + (exp(min(x,0)) - 1);  exp(0)==1 exactly
__device__ __forceinline__ float eluf(float x) {
    return fmaxf(x, 0.f) + (__expf(fminf(x, 0.f)) - 1.f);
}

__device__ __forceinline__ ull pk2(float lo, float hi) {
    ull r;
    asm("mov.b64 %0, {%1, %2};" : "=l"(r) : "f"(lo), "f"(hi));
    return r;
}
__device__ __forceinline__ ull ffma2(ull a, ull b, ull c) {
    ull d;
    asm("fma.rn.f32x2 %0, %1, %2, %3;" : "=l"(d) : "l"(a), "l"(b), "l"(c));
    return d;
}
__device__ __forceinline__ float2 upk2(ull a) {
    float2 v;
    asm("mov.b64 {%0, %1}, %2;" : "=f"(v.x), "=f"(v.y) : "l"(a));
    return v;
}

// ---------------------------------------------------------------------------
// Kernel A: LSH bin assignment. one thread per token.
// ---------------------------------------------------------------------------
__global__ void k_bins(const float* __restrict__ xd,
                       const int* __restrict__ msk,
                       const float* __restrict__ codebook)
{
    __shared__ float cb[25 * 32];
    int tid = threadIdx.x;
    for (int e = tid; e < 25 * 32; e += 128) {
        int h = e >> 5, d = e & 31;
        cb[e] = codebook[d * 100 + h];
    }
    __syncthreads();

    int gid = blockIdx.x * 128 + tid;
    const float* xr = xd + (size_t)gid * DDIM;
    float x[32];
#pragma unroll
    for (int c = 0; c < 8; c++) {
        float4 v = ((const float4*)xr)[c];
        x[c * 4 + 0] = v.x; x[c * 4 + 1] = v.y; x[c * 4 + 2] = v.z; x[c * 4 + 3] = v.w;
    }
    float mul[25];
#pragma unroll
    for (int h = 0; h < 25; h++) {
        float a0 = 0.f, a1 = 0.f, a2 = 0.f, a3 = 0.f;
#pragma unroll
        for (int d = 0; d < 32; d += 4) {
            a0 += x[d + 0] * cb[h * 32 + d + 0];
            a1 += x[d + 1] * cb[h * 32 + d + 1];
            a2 += x[d + 2] * cb[h * 32 + d + 2];
            a3 += x[d + 3] * cb[h * 32 + d + 3];
        }
        mul[h] = (a0 + a1) + (a2 + a3);
    }
    float best = -INFINITY; int arg = 0;
#pragma unroll
    for (int h = 0; h < 25; h++)
        if (mul[h] > best) { best = mul[h]; arg = h; }
#pragma unroll
    for (int h = 0; h < 25; h++) {
        float v = -mul[h];
        if (v > best) { best = v; arg = 25 + h; }
    }
    g_bin_idx[gid] = arg + (msk[gid] != 0 ? 0 : (NBINS - 1));
}

// ---------------------------------------------------------------------------
// Kernel B: stable counting sort per batch -> bins_split
// ---------------------------------------------------------------------------
__global__ void k_sort(float* __restrict__ out)
{
    __shared__ unsigned short hist[128][NKEY];
    __shared__ int key_start[NKEY];
    __shared__ int total[NKEY];

    int t = threadIdx.x;
    int b = blockIdx.x;
    const int* keys = g_bin_idx + b * NTOK;

    for (int k = 0; k < NKEY; k++) hist[t][k] = 0;
    __syncthreads();

    int base = t * 50;
    for (int i = 0; i < 50; i++) hist[t][keys[base + i]]++;
    __syncthreads();

    if (t < NKEY) {
        int run = 0;
        for (int t2 = 0; t2 < 128; t2++) {
            int c = hist[t2][t];
            hist[t2][t] = (unsigned short)run;
            run += c;
        }
        total[t] = run;
    }
    __syncthreads();
    if (t == 0) {
        int s = 0;
        for (int k = 0; k < NKEY; k++) { key_start[k] = s; s += total[k]; }
    }
    __syncthreads();

    int*   ob = g_bins + b * NTOK;
    float* of = out + (size_t)b * NTOK;
    for (int i = 0; i < 50; i++) {
        int n = base + i;
        int k = keys[n];
        int pos = key_start[k] + (int)hist[t][k];
        hist[t][k]++;
        ob[pos] = n;
        of[pos] = (float)n;
    }
}

// ---------------------------------------------------------------------------
// Kernel D: pairwise FFN -> dm, fused with the feature/mask gather.
// dm blocks (blk < 1600): tile x jb(quadrant of j) x iq(quarter of i).
//   128 threads (4 warps), 3 CTA/SM. Warp: lane owns j; 4 passes of 2 i's.
//   Weight row streamed once per k feeds both i's (o-packed FFMA2 accs).
// gather blocks (blk >= 1600): copy x_features_binned + msk_f_binned.
// ---------------------------------------------------------------------------
__global__ void __launch_bounds__(128, 3) k_dm(
    const float* __restrict__ xd, const float* __restrict__ xf,
    const int* __restrict__ msk,
    const float* __restrict__ W1, const float* __restrict__ b1,
    const float* __restrict__ W2, const float* __restrict__ b2,
    const float* __restrict__ W3, const float* __restrict__ b3,
    float* __restrict__ out)
{
    extern __shared__ float sm[];
    int*   idxI = (int*)sm;          // 32
    int*   idxJ = (int*)(sm + 32);   // 32
    float* miS  = sm + 64;           // 32
    float* mjS  = sm + 96;           // 32
    float* W1s  = sm + 128;          // 2048
    float* W2s  = sm + 2176;         // 1024
    float* W3s  = sm + 3200;         // 1024
    float* b2s  = sm + 4224;         // 32
    float* b3s  = sm + 4256;         // 32
    float* XdS  = sm + 4288;         // 64*36 = 2304 (rows 0-31: i, 32-63: j)
    float* US   = sm + 6592;         // 32*36 = 1152
    float* VTS  = sm + 7744;         // 32k x 32j = 1024
    // total 8768 floats = 35072 B

    int tid = threadIdx.x;
    int blk = blockIdx.x;

    // ---------------- gather path ----------------
    if (blk >= DM_BLOCKS) {
        int g = blk - DM_BLOCKS;             // 0..199, 64 rows each
        if (tid < 64) {
            int gid = g * 64 + tid;
            int bb = gid / NTOK;
            int src = g_bins[gid];
            out[O3 + gid] = (msk[bb * NTOK + src] != 0) ? 1.f : 0.f;
        }
        int base = g * 64;
        float4* dst = (float4*)(out + O1);
#pragma unroll 4
        for (int p = 0; p < 32; p++) {
            int idx = p * 128 + tid;         // 0..4095
            int r = idx >> 6, c = idx & 63;
            int gid = base + r;
            int bb = gid / NTOK;
            int src = g_bins[gid];
            dst[(size_t)gid * 64 + c] =
                ((const float4*)(xf + ((size_t)(bb * NTOK + src)) * FDIM))[c];
        }
        return;
    }

    // ---------------- dm path ----------------
    int tile = blk >> 4;                 // 0..99
    int jb   = (blk >> 2) & 3;           // j quadrant
    int iq   = blk & 3;                  // i quarter
    int b    = tile / NBINS;
    int bin  = tile % NBINS;
    int w    = tid >> 5, lane = tid & 31;

    if (tid < 64) {
        int half = tid >> 5;             // 0: i-chunk, 1: j-chunk
        int t = tid & 31;
        int off = half ? (jb * 32) : (iq * 32);
        int row = g_bins[b * NTOK + bin * BINSZ + off + t];
        float m = (msk[b * NTOK + row] != 0) ? 1.f : 0.f;
        if (half) { idxJ[t] = row; mjS[t] = m; }
        else      { idxI[t] = row; miS[t] = m; }
    }
    __syncthreads();

    float mjl = mjS[lane];
    unsigned act = __ballot_sync(0xffffffffu, mjl != 0.f);
    if (act == 0) {
        // entire j-quadrant masked: zero 32i x 32j x 32o
        float4 z4 = make_float4(0.f, 0.f, 0.f, 0.f);
        float4* basep = (float4*)(out + O2 +
            (((size_t)tile * BINSZ + iq * 32) * BINSZ + jb * 32) * 32);
        for (int e = tid; e < 8192; e += 128) {
            int i = e >> 8, rem = e & 255;
            basep[(size_t)i * 1024 + rem] = z4;
        }
        return;
    }

    // stage weights
    for (int e = tid; e < 2048; e += 128) W1s[e] = W1[e];
    for (int e = tid; e < 1024; e += 128) { W2s[e] = W2[e]; W3s[e] = W3[e]; }
    if (tid < 32) { b2s[tid] = b2[tid]; b3s[tid] = b3[tid]; }

    // gather 64 x_dist rows (i-chunk rows 0-31, j-chunk rows 32-63), stride 36
#pragma unroll
    for (int c = 0; c < 4; c++) {
        int idx = c * 128 + tid;             // 0..511
        int r = idx >> 3, q = idx & 7;
        int row = (r < 32) ? idxI[r] : idxJ[r - 32];
        float4 v = ((const float4*)(xd + ((size_t)(b * NTOK + row)) * DDIM))[q];
        *(float4*)(XdS + r * 36 + q * 4) = v;
    }
    __syncthreads();

    // U[i][o] (32 i-local rows) and V^T[k][j] (32 j rows)
    {
        int r = tid >> 2, og = (tid & 3) * 8;
        float acc[8];
#pragma unroll
        for (int c = 0; c < 8; c++) acc[c] = b1[og + c];
#pragma unroll
        for (int d = 0; d < 32; d++) {
            float xv = XdS[r * 36 + d];
            const float* wr = W1s + d * 32 + og;
#pragma unroll
            for (int c = 0; c < 8; c++) acc[c] += xv * wr[c];
        }
        float* u = US + r * 36 + og;
#pragma unroll
        for (int c = 0; c < 8; c++) u[c] = acc[c];

        float av[8];
#pragma unroll
        for (int c = 0; c < 8; c++) av[c] = 0.f;
#pragma unroll
        for (int d = 0; d < 32; d++) {
            float xv = XdS[(32 + r) * 36 + d];
            const float* wr = W1s + (32 + d) * 32 + og;
#pragma unroll
            for (int c = 0; c < 8; c++) av[c] += xv * wr[c];
        }
#pragma unroll
        for (int c = 0; c < 8; c++) VTS[(og + c) * 32 + r] = av[c];
    }
    __syncthreads();

    const ulonglong2* b2v = (const ulonglong2*)b2s;
    const ulonglong2* b3v = (const ulonglong2*)b3s;
    const float4 z4 = make_float4(0.f, 0.f, 0.f, 0.f);

#pragma unroll 1
    for (int t = 0; t < 4; t++) {
        int il0 = w * 8 + t * 2, il1 = il0 + 1;
        float mi0 = miS[il0], mi1 = miS[il1];
        float* rp0 = out + O2 +
            (((size_t)tile * BINSZ + iq * 32 + il0) * BINSZ + jb * 32 + lane) * 32;
        float* rp1 = rp0 + (size_t)BINSZ * 32;

        if (mi0 == 0.f && mi1 == 0.f) {
            float4* a0 = (float4*)rp0;
            float4* a1 = (float4*)rp1;
#pragma unroll
            for (int q = 0; q < 8; q++) { a0[q] = z4; a1[q] = z4; }
            continue;
        }

        // h1 for both i's (lane's j), registers only
        float h1a[32], h1b[32];
        {
            const float4* U0 = (const float4*)(US + il0 * 36);
            const float4* U1 = (const float4*)(US + il1 * 36);
#pragma unroll
            for (int k4 = 0; k4 < 8; k4++) {
                float4 u0 = U0[k4];
                float4 u1 = U1[k4];
                float v0 = VTS[(k4 * 4 + 0) * 32 + lane];
                float v1 = VTS[(k4 * 4 + 1) * 32 + lane];
                float v2 = VTS[(k4 * 4 + 2) * 32 + lane];
                float v3 = VTS[(k4 * 4 + 3) * 32 + lane];
                h1a[k4 * 4 + 0] = eluf(u0.x + v0);
                h1a[k4 * 4 + 1] = eluf(u0.y + v1);
                h1a[k4 * 4 + 2] = eluf(u0.z + v2);
                h1a[k4 * 4 + 3] = eluf(u0.w + v3);
                h1b[k4 * 4 + 0] = eluf(u1.x + v0);
                h1b[k4 * 4 + 1] = eluf(u1.y + v1);
                h1b[k4 * 4 + 2] = eluf(u1.z + v2);
                h1b[k4 * 4 + 3] = eluf(u1.w + v3);
            }
        }

        // layer 2: o-packed accs, weight row shared by both i's
        ull A0[16], A1[16];
#pragma unroll
        for (int q = 0; q < 8; q++) {
            ulonglong2 bb = b2v[q];
            A0[2 * q] = bb.x; A0[2 * q + 1] = bb.y;
            A1[2 * q] = bb.x; A1[2 * q + 1] = bb.y;
        }
#pragma unroll
        for (int k = 0; k < 32; k++) {
            ull ha = pk2(h1a[k], h1a[k]);
            ull hb = pk2(h1b[k], h1b[k]);
            const ulonglong2* wr = (const ulonglong2*)(W2s + k * 32);
#pragma unroll
            for (int q = 0; q < 8; q++) {
                ulonglong2 wv = wr[q];
                A0[2 * q]     = ffma2(ha, wv.x, A0[2 * q]);
                A0[2 * q + 1] = ffma2(ha, wv.y, A0[2 * q + 1]);
                A1[2 * q]     = ffma2(hb, wv.x, A1[2 * q]);
                A1[2 * q + 1] = ffma2(hb, wv.y, A1[2 * q + 1]);
            }
        }
        // h2 overwrites h1 registers
#pragma unroll
        for (int a = 0; a < 16; a++) {
            float2 f0 = upk2(A0[a]);
            float2 f1 = upk2(A1[a]);
            h1a[2 * a] = eluf(f0.x); h1a[2 * a + 1] = eluf(f0.y);
            h1b[2 * a] = eluf(f1.x); h1b[2 * a + 1] = eluf(f1.y);
        }

        // layer 3
#pragma unroll
        for (int q = 0; q < 8; q++) {
            ulonglong2 bb = b3v[q];
            A0[2 * q] = bb.x; A0[2 * q + 1] = bb.y;
            A1[2 * q] = bb.x; A1[2 * q + 1] = bb.y;
        }
#pragma unroll
        for (int k = 0; k < 32; k++) {
            ull ha = pk2(h1a[k], h1a[k]);
            ull hb = pk2(h1b[k], h1b[k]);
            const ulonglong2* wr = (const ulonglong2*)(W3s + k * 32);
#pragma unroll
            for (int q = 0; q < 8; q++) {
                ulonglong2 wv = wr[q];
                A0[2 * q]     = ffma2(ha, wv.x, A0[2 * q]);
                A0[2 * q + 1] = ffma2(ha, wv.y, A0[2 * q + 1]);
                A1[2 * q]     = ffma2(hb, wv.x, A1[2 * q]);
                A1[2 * q + 1] = ffma2(hb, wv.y, A1[2 * q + 1]);
            }
        }

        // final elu, exact 0/1 mask multiply, vectorized stores
        float s0 = mi0 * mjl, s1 = mi1 * mjl;
        float4* o0 = (float4*)rp0;
        float4* o1 = (float4*)rp1;
#pragma unroll
        for (int e = 0; e < 8; e++) {
            float2 fa = upk2(A0[2 * e]);
            float2 fb = upk2(A0[2 * e + 1]);
            float4 r;
            r.x = eluf(fa.x) * s0; r.y = eluf(fa.y) * s0;
            r.z = eluf(fb.x) * s0; r.w = eluf(fb.y) * s0;
            o0[e] = r;
            float2 ga = upk2(A1[2 * e]);
            float2 gb = upk2(A1[2 * e + 1]);
            float4 r1;
            r1.x = eluf(ga.x) * s1; r1.y = eluf(ga.y) * s1;
            r1.z = eluf(gb.x) * s1; r1.w = eluf(gb.y) * s1;
            o1[e] = r1;
        }
    }
}

// ---------------------------------------------------------------------------
extern "C" void kernel_launch(void* const* d_in, const int* in_sizes, int n_in,
                              void* d_out, int out_size)
{
    const float* xd  = (const float*)d_in[0];
    const float* xf  = (const float*)d_in[1];
    const int*   mk  = (const int*)d_in[2];
    const float* cb  = (const float*)d_in[3];
    const float* W1  = (const float*)d_in[4];
    const float* b1  = (const float*)d_in[5];
    const float* W2  = (const float*)d_in[6];
    const float* b2  = (const float*)d_in[7];
    const float* W3  = (const float*)d_in[8];
    const float* b3  = (const float*)d_in[9];
    float* out = (float*)d_out;

    k_bins<<<100, 128>>>(xd, mk, cb);
    k_sort<<<BTCH, 128>>>(out);

    cudaFuncSetAttribute(k_dm, cudaFuncAttributeMaxDynamicSharedMemorySize, 35072);
    k_dm<<<DM_BLOCKS + GATHER_BLOCKS, 128, 35072>>>(
        xd, xf, mk, W1, b1, W2, b2, W3, b3, out);
}

// round 8
// speedup vs baseline: 2.8089x; 1.0004x over previous
#include <cuda_runtime.h>
#include <math.h>

#define BTCH 2
#define NTOK 6400
#define NBINS 50
#define BINSZ 128
#define DDIM 32
#define FDIM 256
#define NKEY 100

// output packing (floats): [bins_split | x_features_binned | dm | msk_f_binned]
#define O1 12800ULL
#define O2 3289600ULL
#define O3 55718400ULL

#define DM_BLOCKS 1600
#define GATHER_BLOCKS 200

typedef unsigned long long ull;

__device__ int g_bin_idx[BTCH * NTOK];
__device__ int g_bins[BTCH * NTOK];

// fast elu: max(x,0) + (exp(min(x,0)) - 1);  exp(0)==1 exactly
__device__ __forceinline__ float eluf(float x) {
    return fmaxf(x, 0.f) + (__expf(fminf(x, 0.f)) - 1.f);
}

__device__ __forceinline__ ull pk2(float lo, float hi) {
    ull r;
    asm("mov.b64 %0, {%1, %2};" : "=l"(r) : "f"(lo), "f"(hi));
    return r;
}
__device__ __forceinline__ ull ffma2(ull a, ull b, ull c) {
    ull d;
    asm("fma.rn.f32x2 %0, %1, %2, %3;" : "=l"(d) : "l"(a), "l"(b), "l"(c));
    return d;
}
__device__ __forceinline__ float2 upk2(ull a) {
    float2 v;
    asm("mov.b64 {%0, %1}, %2;" : "=f"(v.x), "=f"(v.y) : "l"(a));
    return v;
}

// one k-step of a 32-wide o-packed dual-i accumulation
__device__ __forceinline__ void acc_step(float fa, float fb, const float* Wrow,
                                         ull* A0, ull* A1)
{
    ull ha = pk2(fa, fa), hb = pk2(fb, fb);
    const ulonglong2* wr = (const ulonglong2*)Wrow;
#pragma unroll
    for (int q = 0; q < 8; q++) {
        ulonglong2 wv = wr[q];
        A0[2 * q]     = ffma2(ha, wv.x, A0[2 * q]);
        A0[2 * q + 1] = ffma2(ha, wv.y, A0[2 * q + 1]);
        A1[2 * q]     = ffma2(hb, wv.x, A1[2 * q]);
        A1[2 * q + 1] = ffma2(hb, wv.y, A1[2 * q + 1]);
    }
}

// ---------------------------------------------------------------------------
// Kernel A: LSH bin assignment. one thread per token.
// ---------------------------------------------------------------------------
__global__ void k_bins(const float* __restrict__ xd,
                       const int* __restrict__ msk,
                       const float* __restrict__ codebook)
{
    __shared__ float cb[25 * 32];
    int tid = threadIdx.x;
    for (int e = tid; e < 25 * 32; e += 128) {
        int h = e >> 5, d = e & 31;
        cb[e] = codebook[d * 100 + h];
    }
    __syncthreads();

    int gid = blockIdx.x * 128 + tid;
    const float* xr = xd + (size_t)gid * DDIM;
    float x[32];
#pragma unroll
    for (int c = 0; c < 8; c++) {
        float4 v = ((const float4*)xr)[c];
        x[c * 4 + 0] = v.x; x[c * 4 + 1] = v.y; x[c * 4 + 2] = v.z; x[c * 4 + 3] = v.w;
    }
    float mul[25];
#pragma unroll
    for (int h = 0; h < 25; h++) {
        float a0 = 0.f, a1 = 0.f, a2 = 0.f, a3 = 0.f;
#pragma unroll
        for (int d = 0; d < 32; d += 4) {
            a0 += x[d + 0] * cb[h * 32 + d + 0];
            a1 += x[d + 1] * cb[h * 32 + d + 1];
            a2 += x[d + 2] * cb[h * 32 + d + 2];
            a3 += x[d + 3] * cb[h * 32 + d + 3];
        }
        mul[h] = (a0 + a1) + (a2 + a3);
    }
    float best = -INFINITY; int arg = 0;
#pragma unroll
    for (int h = 0; h < 25; h++)
        if (mul[h] > best) { best = mul[h]; arg = h; }
#pragma unroll
    for (int h = 0; h < 25; h++) {
        float v = -mul[h];
        if (v > best) { best = v; arg = 25 + h; }
    }
    g_bin_idx[gid] = arg + (msk[gid] != 0 ? 0 : (NBINS - 1));
}

// ---------------------------------------------------------------------------
// Kernel B: stable counting sort per batch -> bins_split
// ---------------------------------------------------------------------------
__global__ void k_sort(float* __restrict__ out)
{
    __shared__ unsigned short hist[128][NKEY];
    __shared__ int key_start[NKEY];
    __shared__ int total[NKEY];

    int t = threadIdx.x;
    int b = blockIdx.x;
    const int* keys = g_bin_idx + b * NTOK;

    for (int k = 0; k < NKEY; k++) hist[t][k] = 0;
    __syncthreads();

    int base = t * 50;
    for (int i = 0; i < 50; i++) hist[t][keys[base + i]]++;
    __syncthreads();

    if (t < NKEY) {
        int run = 0;
        for (int t2 = 0; t2 < 128; t2++) {
            int c = hist[t2][t];
            hist[t2][t] = (unsigned short)run;
            run += c;
        }
        total[t] = run;
    }
    __syncthreads();
    if (t == 0) {
        int s = 0;
        for (int k = 0; k < NKEY; k++) { key_start[k] = s; s += total[k]; }
    }
    __syncthreads();

    int*   ob = g_bins + b * NTOK;
    float* of = out + (size_t)b * NTOK;
    for (int i = 0; i < 50; i++) {
        int n = base + i;
        int k = keys[n];
        int pos = key_start[k] + (int)hist[t][k];
        hist[t][k]++;
        ob[pos] = n;
        of[pos] = (float)n;
    }
}

// ---------------------------------------------------------------------------
// Kernel D: pairwise FFN -> dm, fused with the feature/mask gather.
// dm blocks: tile x jb x iq; 128 threads, 3 CTA/SM; warp: lane owns j,
// 4 passes of 2 i's. h1 is STREAMED inside the layer-2 k-loop (never stored),
// keeping peak live registers < 160 (no spills).
// ---------------------------------------------------------------------------
__global__ void __launch_bounds__(128, 3) k_dm(
    const float* __restrict__ xd, const float* __restrict__ xf,
    const int* __restrict__ msk,
    const float* __restrict__ W1, const float* __restrict__ b1,
    const float* __restrict__ W2, const float* __restrict__ b2,
    const float* __restrict__ W3, const float* __restrict__ b3,
    float* __restrict__ out)
{
    extern __shared__ float sm[];
    int*   idxI = (int*)sm;          // 32
    int*   idxJ = (int*)(sm + 32);   // 32
    float* miS  = sm + 64;           // 32
    float* mjS  = sm + 96;           // 32
    float* W1s  = sm + 128;          // 2048
    float* W2s  = sm + 2176;         // 1024
    float* W3s  = sm + 3200;         // 1024
    float* b2s  = sm + 4224;         // 32
    float* b3s  = sm + 4256;         // 32
    float* XdS  = sm + 4288;         // 64*36 = 2304 (rows 0-31: i, 32-63: j)
    float* US   = sm + 6592;         // 32*36 = 1152
    float* VTS  = sm + 7744;         // 32k x 32j = 1024
    // total 8768 floats = 35072 B

    int tid = threadIdx.x;
    int blk = blockIdx.x;

    // ---------------- gather path ----------------
    if (blk >= DM_BLOCKS) {
        int g = blk - DM_BLOCKS;             // 0..199, 64 rows each
        if (tid < 64) {
            int gid = g * 64 + tid;
            int bb = gid / NTOK;
            int src = g_bins[gid];
            out[O3 + gid] = (msk[bb * NTOK + src] != 0) ? 1.f : 0.f;
        }
        int base = g * 64;
        float4* dst = (float4*)(out + O1);
#pragma unroll 4
        for (int p = 0; p < 32; p++) {
            int idx = p * 128 + tid;         // 0..4095
            int r = idx >> 6, c = idx & 63;
            int gid = base + r;
            int bb = gid / NTOK;
            int src = g_bins[gid];
            dst[(size_t)gid * 64 + c] =
                ((const float4*)(xf + ((size_t)(bb * NTOK + src)) * FDIM))[c];
        }
        return;
    }

    // ---------------- dm path ----------------
    int tile = blk >> 4;                 // 0..99
    int jb   = (blk >> 2) & 3;           // j quadrant
    int iq   = blk & 3;                  // i quarter
    int b    = tile / NBINS;
    int bin  = tile % NBINS;
    int w    = tid >> 5, lane = tid & 31;

    if (tid < 64) {
        int half = tid >> 5;             // 0: i-chunk, 1: j-chunk
        int t = tid & 31;
        int off = half ? (jb * 32) : (iq * 32);
        int row = g_bins[b * NTOK + bin * BINSZ + off + t];
        float m = (msk[b * NTOK + row] != 0) ? 1.f : 0.f;
        if (half) { idxJ[t] = row; mjS[t] = m; }
        else      { idxI[t] = row; miS[t] = m; }
    }
    __syncthreads();

    float mjl = mjS[lane];
    unsigned act = __ballot_sync(0xffffffffu, mjl != 0.f);
    if (act == 0) {
        float4 z4 = make_float4(0.f, 0.f, 0.f, 0.f);
        float4* basep = (float4*)(out + O2 +
            (((size_t)tile * BINSZ + iq * 32) * BINSZ + jb * 32) * 32);
        for (int e = tid; e < 8192; e += 128) {
            int i = e >> 8, rem = e & 255;
            basep[(size_t)i * 1024 + rem] = z4;
        }
        return;
    }

    // stage weights
    for (int e = tid; e < 2048; e += 128) W1s[e] = W1[e];
    for (int e = tid; e < 1024; e += 128) { W2s[e] = W2[e]; W3s[e] = W3[e]; }
    if (tid < 32) { b2s[tid] = b2[tid]; b3s[tid] = b3[tid]; }

    // gather 64 x_dist rows (i-chunk rows 0-31, j-chunk rows 32-63), stride 36
#pragma unroll
    for (int c = 0; c < 4; c++) {
        int idx = c * 128 + tid;             // 0..511
        int r = idx >> 3, q = idx & 7;
        int row = (r < 32) ? idxI[r] : idxJ[r - 32];
        float4 v = ((const float4*)(xd + ((size_t)(b * NTOK + row)) * DDIM))[q];
        *(float4*)(XdS + r * 36 + q * 4) = v;
    }
    __syncthreads();

    // U[i][o] (32 i-local rows) and V^T[k][j] (32 j rows)
    {
        int r = tid >> 2, og = (tid & 3) * 8;
        float acc[8];
#pragma unroll
        for (int c = 0; c < 8; c++) acc[c] = b1[og + c];
#pragma unroll
        for (int d = 0; d < 32; d++) {
            float xv = XdS[r * 36 + d];
            const float* wr = W1s + d * 32 + og;
#pragma unroll
            for (int c = 0; c < 8; c++) acc[c] += xv * wr[c];
        }
        float* u = US + r * 36 + og;
#pragma unroll
        for (int c = 0; c < 8; c++) u[c] = acc[c];

        float av[8];
#pragma unroll
        for (int c = 0; c < 8; c++) av[c] = 0.f;
#pragma unroll
        for (int d = 0; d < 32; d++) {
            float xv = XdS[(32 + r) * 36 + d];
            const float* wr = W1s + (32 + d) * 32 + og;
#pragma unroll
            for (int c = 0; c < 8; c++) av[c] += xv * wr[c];
        }
#pragma unroll
        for (int c = 0; c < 8; c++) VTS[(og + c) * 32 + r] = av[c];
    }
    __syncthreads();

    const ulonglong2* b2v = (const ulonglong2*)b2s;
    const ulonglong2* b3v = (const ulonglong2*)b3s;
    const float4 z4 = make_float4(0.f, 0.f, 0.f, 0.f);

#pragma unroll 1
    for (int t = 0; t < 4; t++) {
        int il0 = w * 8 + t * 2, il1 = il0 + 1;
        float mi0 = miS[il0], mi1 = miS[il1];
        float* rp0 = out + O2 +
            (((size_t)tile * BINSZ + iq * 32 + il0) * BINSZ + jb * 32 + lane) * 32;
        float* rp1 = rp0 + (size_t)BINSZ * 32;

        if (mi0 == 0.f && mi1 == 0.f) {
            float4* a0 = (float4*)rp0;
            float4* a1 = (float4*)rp1;
#pragma unroll
            for (int q = 0; q < 8; q++) { a0[q] = z4; a1[q] = z4; }
            continue;
        }

        // ---- layer 2 with h1 streamed (never stored) ----
        ull A0[16], A1[16];
#pragma unroll
        for (int q = 0; q < 8; q++) {
            ulonglong2 bb = b2v[q];
            A0[2 * q] = bb.x; A0[2 * q + 1] = bb.y;
            A1[2 * q] = bb.x; A1[2 * q + 1] = bb.y;
        }
        {
            const float4* U0 = (const float4*)(US + il0 * 36);
            const float4* U1 = (const float4*)(US + il1 * 36);
#pragma unroll
            for (int k4 = 0; k4 < 8; k4++) {
                float4 u0 = U0[k4];
                float4 u1 = U1[k4];
                int k = k4 * 4;
                float v0 = VTS[(k + 0) * 32 + lane];
                acc_step(eluf(u0.x + v0), eluf(u1.x + v0), W2s + (k + 0) * 32, A0, A1);
                float v1 = VTS[(k + 1) * 32 + lane];
                acc_step(eluf(u0.y + v1), eluf(u1.y + v1), W2s + (k + 1) * 32, A0, A1);
                float v2 = VTS[(k + 2) * 32 + lane];
                acc_step(eluf(u0.z + v2), eluf(u1.z + v2), W2s + (k + 2) * 32, A0, A1);
                float v3 = VTS[(k + 3) * 32 + lane];
                acc_step(eluf(u0.w + v3), eluf(u1.w + v3), W2s + (k + 3) * 32, A0, A1);
            }
        }

        // h2 = elu(acc)
        float h2a[32], h2b[32];
#pragma unroll
        for (int a = 0; a < 16; a++) {
            float2 f0 = upk2(A0[a]);
            float2 f1 = upk2(A1[a]);
            h2a[2 * a] = eluf(f0.x); h2a[2 * a + 1] = eluf(f0.y);
            h2b[2 * a] = eluf(f1.x); h2b[2 * a + 1] = eluf(f1.y);
        }

        // ---- layer 3 ----
#pragma unroll
        for (int q = 0; q < 8; q++) {
            ulonglong2 bb = b3v[q];
            A0[2 * q] = bb.x; A0[2 * q + 1] = bb.y;
            A1[2 * q] = bb.x; A1[2 * q + 1] = bb.y;
        }
#pragma unroll
        for (int k = 0; k < 32; k++)
            acc_step(h2a[k], h2b[k], W3s + k * 32, A0, A1);

        // final elu, exact 0/1 mask multiply, vectorized stores
        float s0 = mi0 * mjl, s1 = mi1 * mjl;
        float4* o0 = (float4*)rp0;
        float4* o1 = (float4*)rp1;
#pragma unroll
        for (int e = 0; e < 8; e++) {
            float2 fa = upk2(A0[2 * e]);
            float2 fb = upk2(A0[2 * e + 1]);
            float4 r;
            r.x = eluf(fa.x) * s0; r.y = eluf(fa.y) * s0;
            r.z = eluf(fb.x) * s0; r.w = eluf(fb.y) * s0;
            o0[e] = r;
            float2 ga = upk2(A1[2 * e]);
            float2 gb = upk2(A1[2 * e + 1]);
            float4 r1;
            r1.x = eluf(ga.x) * s1; r1.y = eluf(ga.y) * s1;
            r1.z = eluf(gb.x) * s1; r1.w = eluf(gb.y) * s1;
            o1[e] = r1;
        }
    }
}

// ---------------------------------------------------------------------------
extern "C" void kernel_launch(void* const* d_in, const int* in_sizes, int n_in,
                              void* d_out, int out_size)
{
    const float* xd  = (const float*)d_in[0];
    const float* xf  = (const float*)d_in[1];
    const int*   mk  = (const int*)d_in[2];
    const float* cb  = (const float*)d_in[3];
    const float* W1  = (const float*)d_in[4];
    const float* b1  = (const float*)d_in[5];
    const float* W2  = (const float*)d_in[6];
    const float* b2  = (const float*)d_in[7];
    const float* W3  = (const float*)d_in[8];
    const float* b3  = (const float*)d_in[9];
    float* out = (float*)d_out;

    k_bins<<<100, 128>>>(xd, mk, cb);
    k_sort<<<BTCH, 128>>>(out);

    cudaFuncSetAttribute(k_dm, cudaFuncAttributeMaxDynamicSharedMemorySize, 35072);
    k_dm<<<DM_BLOCKS + GATHER_BLOCKS, 128, 35072>>>(
        xd, xf, mk, W1, b1, W2, b2, W3, b3, out);
}